// round 2
// baseline (speedup 1.0000x reference)
#include <cuda_runtime.h>
#include <math.h>

#define BATCH 8192
#define NN    8
#define CLCH  64
#define ROWS  (BATCH*NN)   // 65536

// Scratch (static device globals; allocation-free per harness rules)
__device__ float g_AB[(size_t)ROWS * 512];  // per row: [A_rel(128) | B_rel(128) | A_att(128) | B_att(128)]
__device__ float g_SD[(size_t)ROWS * 64];   // self_dyn per (b,i)

__device__ __forceinline__ float eluf(float x) {
    return x > 0.f ? x : (__expf(x) - 1.f);
}
__device__ __forceinline__ float getc(const float4& v, int q) {
    return q == 0 ? v.x : q == 1 ? v.y : q == 2 ? v.z : v.w;
}

// C[64x64] tile GEMM: A [64][AS] (row r, k), B [K][BS] (k, col c), 256 threads,
// each thread computes 4x4 microtile at (ty*4, tx*4).
template<int K, int AS, int BS>
__device__ __forceinline__ void tile_gemm(const float* __restrict__ A,
                                          const float* __restrict__ B,
                                          int ty, int tx, float acc[4][4])
{
#pragma unroll 8
    for (int k = 0; k < K; k += 4) {
        float4 a0 = *(const float4*)(A + (ty*4+0)*AS + k);
        float4 a1 = *(const float4*)(A + (ty*4+1)*AS + k);
        float4 a2 = *(const float4*)(A + (ty*4+2)*AS + k);
        float4 a3 = *(const float4*)(A + (ty*4+3)*AS + k);
#pragma unroll
        for (int q = 0; q < 4; q++) {
            float4 bq = *(const float4*)(B + (k+q)*BS + tx*4);
            float b0 = bq.x, b1 = bq.y, b2 = bq.z, b3 = bq.w;
            float v0 = getc(a0,q), v1 = getc(a1,q), v2 = getc(a2,q), v3 = getc(a3,q);
            acc[0][0] = fmaf(v0,b0,acc[0][0]); acc[0][1] = fmaf(v0,b1,acc[0][1]);
            acc[0][2] = fmaf(v0,b2,acc[0][2]); acc[0][3] = fmaf(v0,b3,acc[0][3]);
            acc[1][0] = fmaf(v1,b0,acc[1][0]); acc[1][1] = fmaf(v1,b1,acc[1][1]);
            acc[1][2] = fmaf(v1,b2,acc[1][2]); acc[1][3] = fmaf(v1,b3,acc[1][3]);
            acc[2][0] = fmaf(v2,b0,acc[2][0]); acc[2][1] = fmaf(v2,b1,acc[2][1]);
            acc[2][2] = fmaf(v2,b2,acc[2][2]); acc[2][3] = fmaf(v2,b3,acc[2][3]);
            acc[3][0] = fmaf(v3,b0,acc[3][0]); acc[3][1] = fmaf(v3,b1,acc[3][1]);
            acc[3][2] = fmaf(v3,b2,acc[3][2]); acc[3][3] = fmaf(v3,b3,acc[3][3]);
        }
    }
}

#define ZERO16(acc) { _Pragma("unroll") for (int _i=0;_i<4;_i++) _Pragma("unroll") for (int _j=0;_j<4;_j++) acc[_i][_j]=0.f; }

// ---------------------------------------------------------------------------
// K1: per 64-row tile: s_enc, h, self_dyn -> g_SD, and AB projection -> g_AB
// smem: SH [64][68] (s, then h) | EN [64][68] (s_enc) | WT [64][68] | BV [64]
// ---------------------------------------------------------------------------
__global__ __launch_bounds__(256, 1)
void k1_kernel(const float* __restrict__ s,
               const float* __restrict__ W_enc,  const float* __restrict__ b_enc,
               const float* __restrict__ W_self0, const float* __restrict__ b_self0,
               const float* __restrict__ W_self1, const float* __restrict__ b_self1,
               const float* __restrict__ W_rel0,  const float* __restrict__ W_att0)
{
    extern __shared__ float sm[];
    float* SH = sm;               // 64*68
    float* EN = sm + 4352;        // 64*68
    float* WT = sm + 8704;        // 64*68
    float* BV = sm + 13056;       // 64

    const int tid = threadIdx.x;
    const int tx = tid & 15, ty = tid >> 4;
    const int row0 = blockIdx.x * 64;

    // load s tile + W_enc
    for (int idx = tid; idx < 4096; idx += 256) {
        int r = idx >> 6, c = idx & 63;
        SH[r*68+c] = s[(size_t)(row0 + r) * 64 + c];
        WT[r*68+c] = W_enc[idx];
    }
    if (tid < 64) BV[tid] = b_enc[tid];
    __syncthreads();

    float acc[4][4];
    // s_enc = concat(s[:2], (s@W_enc + b)[2:])
    ZERO16(acc);
    tile_gemm<64,68,68>(SH, WT, ty, tx, acc);
#pragma unroll
    for (int i = 0; i < 4; i++) {
        int r = ty*4 + i;
#pragma unroll
        for (int j = 0; j < 4; j++) {
            int c = tx*4 + j;
            float v = acc[i][j] + BV[c];
            if (c < 2) v = SH[r*68+c];
            EN[r*68+c] = v;
        }
    }
    __syncthreads();

    // h = elu(s_enc @ W_self0 + b)
    for (int idx = tid; idx < 4096; idx += 256) WT[(idx>>6)*68 + (idx&63)] = W_self0[idx];
    if (tid < 64) BV[tid] = b_self0[tid];
    __syncthreads();
    ZERO16(acc);
    tile_gemm<64,68,68>(EN, WT, ty, tx, acc);
    __syncthreads();   // SH (s) dead; safe to overwrite with h after all reads done
#pragma unroll
    for (int i = 0; i < 4; i++) {
        int r = ty*4 + i;
#pragma unroll
        for (int j = 0; j < 4; j++) {
            int c = tx*4 + j;
            SH[r*68+c] = eluf(acc[i][j] + BV[c]);
        }
    }
    __syncthreads();

    // self_dyn = h @ W_self1 + b + h  -> g_SD
    for (int idx = tid; idx < 4096; idx += 256) WT[(idx>>6)*68 + (idx&63)] = W_self1[idx];
    if (tid < 64) BV[tid] = b_self1[tid];
    __syncthreads();
    ZERO16(acc);
    tile_gemm<64,68,68>(SH, WT, ty, tx, acc);
#pragma unroll
    for (int i = 0; i < 4; i++) {
        int r = ty*4 + i;
        float4 v;
        v.x = acc[i][0] + BV[tx*4+0] + SH[r*68 + tx*4+0];
        v.y = acc[i][1] + BV[tx*4+1] + SH[r*68 + tx*4+1];
        v.z = acc[i][2] + BV[tx*4+2] + SH[r*68 + tx*4+2];
        v.w = acc[i][3] + BV[tx*4+3] + SH[r*68 + tx*4+3];
        *(float4*)&g_SD[(size_t)(row0 + r) * 64 + tx*4] = v;
    }

    // AB = s_enc @ [Wa_rel | Wb_rel | Wa_att | Wb_att]  (64 -> 512), 8 chunks
    for (int ch = 0; ch < 8; ch++) {
        __syncthreads();
        for (int idx = tid; idx < 4096; idx += 256) {
            int k = idx >> 6, c = idx & 63;
            int g = ch*64 + c;
            float w;
            if      (g < 128) w = W_rel0[k*128 + g];
            else if (g < 256) w = W_rel0[(64+k)*128 + (g-128)];
            else if (g < 384) w = W_att0[k*128 + (g-256)];
            else              w = W_att0[(64+k)*128 + (g-384)];
            WT[k*68+c] = w;
        }
        __syncthreads();
        ZERO16(acc);
        tile_gemm<64,68,68>(EN, WT, ty, tx, acc);
#pragma unroll
        for (int i = 0; i < 4; i++) {
            int r = ty*4 + i;
            float4 v = make_float4(acc[i][0], acc[i][1], acc[i][2], acc[i][3]);
            *(float4*)&g_AB[(size_t)(row0 + r) * 512 + ch*64 + tx*4] = v;
        }
    }
}

// ---------------------------------------------------------------------------
// K2: pair phase. One block handles K2_BPB batches; heavy pair weights resident
// in smem. Per batch: build X (elu), two 64x128x64 GEMMs, folded epilogue.
// ---------------------------------------------------------------------------
#define K2_BPB 8

__global__ __launch_bounds__(256, 1)
void k2_kernel(const float* __restrict__ s,
               const float* __restrict__ W_rel0, const float* __restrict__ b_rel0,
               const float* __restrict__ W_rel1, const float* __restrict__ b_rel1,
               const float* __restrict__ W_rel2, const float* __restrict__ b_rel2,
               const float* __restrict__ W_att0, const float* __restrict__ b_att0,
               const float* __restrict__ W_att1, const float* __restrict__ b_att1,
               const float* __restrict__ W_att2, const float* __restrict__ b_att2,
               float* __restrict__ out)
{
    extern __shared__ float sm[];
    float* WR1 = sm;              // [128][68]
    float* WA1 = sm + 8704;       // [128][68]
    float* WR2 = sm + 17408;      // [64][64]
    float* XR  = sm + 21504;      // [64][132]
    float* XA  = sm + 29952;      // [64][132]
    float* HR  = sm + 38400;      // [64][68]
    float* HA  = sm + 42752;      // [64][68]
    float* ABs = sm + 47104;      // [8][512]
    float* wdr = sm + 51200;      // [128]
    float* b0r = sm + 51328;
    float* wda = sm + 51456;
    float* b0a = sm + 51584;
    float* b1r = sm + 51712;      // [64]
    float* b1a = sm + 51776;
    float* b2r = sm + 51840;
    float* w2a = sm + 51904;
    float* dst = sm + 51968;      // dist [64]
    float* atp = sm + 52032;      // att  [64]
    float* zv  = sm + 52096;      // z    [64]
    float* psm = sm + 52160;      // pos  [16]

    const int tid = threadIdx.x;
    const int tx = tid & 15, ty = tid >> 4;

    for (int idx = tid; idx < 8192; idx += 256) {
        WR1[(idx>>6)*68 + (idx&63)] = W_rel1[idx];
        WA1[(idx>>6)*68 + (idx&63)] = W_att1[idx];
    }
    for (int idx = tid; idx < 4096; idx += 256) WR2[idx] = W_rel2[idx];
    if (tid < 128) {
        wdr[tid] = W_rel0[128*128 + tid];
        b0r[tid] = b_rel0[tid];
        wda[tid] = W_att0[128*128 + tid];
        b0a[tid] = b_att0[tid];
    }
    if (tid < 64) {
        b1r[tid] = b_rel1[tid];
        b1a[tid] = b_att1[tid];
        b2r[tid] = b_rel2[tid];
        w2a[tid] = W_att2[tid];
    }
    const float b2a = b_att2[0];
    __syncthreads();

    for (int bb = 0; bb < K2_BPB; bb++) {
        const int b = blockIdx.x * K2_BPB + bb;

        // stage AB rows for this batch + positions
        {
            const float4* src = (const float4*)(g_AB + (size_t)b * 4096);
            float4* dab = (float4*)ABs;
            for (int idx = tid; idx < 1024; idx += 256) dab[idx] = src[idx];
        }
        if (tid < 16) psm[tid] = s[(size_t)(b*8 + (tid>>1)) * 64 + (tid & 1)];
        __syncthreads();
        if (tid < 64) {
            int i = tid >> 3, j = tid & 7;
            float dx = psm[2*i]   - psm[2*j];
            float dy = psm[2*i+1] - psm[2*j+1];
            dst[tid] = dx*dx + dy*dy;
        }
        __syncthreads();

        // build X_rel, X_att : elu(A_i + B_j + dist*Wd + b0)
        for (int idx = tid; idx < 8192; idx += 256) {
            int p = idx >> 7, k = idx & 127;
            int i = p >> 3, j = p & 7;
            float d = dst[p];
            XR[p*132+k] = eluf(ABs[i*512 + k]       + ABs[j*512 + 128 + k] + d*wdr[k] + b0r[k]);
            XA[p*132+k] = eluf(ABs[i*512 + 256 + k] + ABs[j*512 + 384 + k] + d*wda[k] + b0a[k]);
        }
        __syncthreads();

        // rel_h2 = elu(X_rel @ W_rel1 + b1r); att_h = elu(X_att @ W_att1 + b1a)
        float acc[4][4];
        ZERO16(acc);
        tile_gemm<128,132,68>(XR, WR1, ty, tx, acc);
#pragma unroll
        for (int i = 0; i < 4; i++)
#pragma unroll
            for (int j = 0; j < 4; j++)
                HR[(ty*4+i)*68 + tx*4+j] = eluf(acc[i][j] + b1r[tx*4+j]);
        ZERO16(acc);
        tile_gemm<128,132,68>(XA, WA1, ty, tx, acc);
#pragma unroll
        for (int i = 0; i < 4; i++)
#pragma unroll
            for (int j = 0; j < 4; j++)
                HA[(ty*4+i)*68 + tx*4+j] = eluf(acc[i][j] + b1a[tx*4+j]);
        __syncthreads();

        // att[p] = sigmoid(att_h[p] . w2a + b2a), masked on diagonal
        if (tid < 64) {
            float a = b2a;
#pragma unroll
            for (int k = 0; k < 64; k++) a = fmaf(HA[tid*68+k], w2a[k], a);
            int i = tid >> 3, j = tid & 7;
            atp[tid] = (i == j) ? 0.f : 1.f / (1.f + __expf(-a));
        }
        __syncthreads();

        // z[c] = sum_p att_p * rel_h2[p][c];  a0 = sum_p att_p
        float zc = 0.f, a0 = 0.f;
        if (tid < 64) {
#pragma unroll
            for (int p = 0; p < 64; p++) {
                float ap = atp[p];
                zc = fmaf(ap, HR[p*68+tid], zc);
                a0 += ap;
            }
            zv[tid] = zc;
        }
        __syncthreads();

        // out = sum_i sd + z + a0*b_rel2 + z @ W_rel2
        if (tid < 64) {
            float o = zc + a0 * b2r[tid];
#pragma unroll
            for (int k = 0; k < 64; k++) o = fmaf(zv[k], WR2[k*64 + tid], o);
#pragma unroll
            for (int i = 0; i < 8; i++) o += g_SD[(size_t)(b*8 + i) * 64 + tid];
            out[(size_t)b * 64 + tid] = o;
        }
        __syncthreads();
    }
}

// ---------------------------------------------------------------------------
extern "C" void kernel_launch(void* const* d_in, const int* in_sizes, int n_in,
                              void* d_out, int out_size)
{
    const float* s       = (const float*)d_in[0];
    const float* W_enc   = (const float*)d_in[1];
    const float* b_enc   = (const float*)d_in[2];
    const float* W_self0 = (const float*)d_in[3];
    const float* b_self0 = (const float*)d_in[4];
    const float* W_self1 = (const float*)d_in[5];
    const float* b_self1 = (const float*)d_in[6];
    const float* W_rel0  = (const float*)d_in[7];
    const float* b_rel0  = (const float*)d_in[8];
    const float* W_rel1  = (const float*)d_in[9];
    const float* b_rel1  = (const float*)d_in[10];
    const float* W_rel2  = (const float*)d_in[11];
    const float* b_rel2  = (const float*)d_in[12];
    const float* W_att0  = (const float*)d_in[13];
    const float* b_att0  = (const float*)d_in[14];
    const float* W_att1  = (const float*)d_in[15];
    const float* b_att1  = (const float*)d_in[16];
    const float* W_att2  = (const float*)d_in[17];
    const float* b_att2  = (const float*)d_in[18];
    float* out = (float*)d_out;

    const int smem1 = 13120 * 4;   // 52,480 B
    const int smem2 = 52176 * 4;   // 208,704 B
    cudaFuncSetAttribute(k1_kernel, cudaFuncAttributeMaxDynamicSharedMemorySize, smem1);
    cudaFuncSetAttribute(k2_kernel, cudaFuncAttributeMaxDynamicSharedMemorySize, smem2);

    k1_kernel<<<ROWS/64, 256, smem1>>>(s, W_enc, b_enc, W_self0, b_self0,
                                       W_self1, b_self1, W_rel0, W_att0);
    k2_kernel<<<BATCH/K2_BPB, 256, smem2>>>(s, W_rel0, b_rel0, W_rel1, b_rel1,
                                            W_rel2, b_rel2, W_att0, b_att0,
                                            W_att1, b_att1, W_att2, b_att2, out);
}

// round 3
// speedup vs baseline: 1.1628x; 1.1628x over previous
#include <cuda_runtime.h>
#include <stdint.h>
#include <math.h>

#define BATCH 8192
#define ROWS  65536
#define K2_BPB 8

// Scratch (static device globals; allocation-free per harness rules)
__device__ float g_AB[(size_t)ROWS * 512];  // per row: [A_rel(128)|B_rel(128)|A_att(128)|B_att(128)]
__device__ float g_SD[(size_t)ROWS * 64];   // self_dyn per (b,i)

__device__ __forceinline__ float eluf(float x) {
    return x > 0.f ? x : (__expf(x) - 1.f);
}
__device__ __forceinline__ uint64_t ffma2(uint64_t a, uint64_t b, uint64_t c) {
    uint64_t d;
    asm("fma.rn.f32x2 %0, %1, %2, %3;" : "=l"(d) : "l"(a), "l"(b), "l"(c));
    return d;
}
__device__ __forceinline__ uint64_t bcast2(float v) {
    uint64_t d;
    asm("mov.b64 %0, {%1, %1};" : "=l"(d) : "f"(v));
    return d;
}
__device__ __forceinline__ float2 u2f(uint64_t u) {
    float2 f;
    asm("mov.b64 {%0, %1}, %2;" : "=f"(f.x), "=f"(f.y) : "l"(u));
    return f;
}
__device__ __forceinline__ float getc(const float4& v, int q) {
    return q == 0 ? v.x : q == 1 ? v.y : q == 2 ? v.z : v.w;
}

// 64x64 output tile, 256 threads, 4x4 microtile per thread, packed f32x2 math.
// A [64][AS] row-major, B [K][BS]. acc[i][jp] holds cols (tx*4+2jp, tx*4+2jp+1).
template<int K, int AS, int BS>
__device__ __forceinline__ void tile_gemm2(const float* __restrict__ A,
                                           const float* __restrict__ B,
                                           int ty, int tx, uint64_t acc[4][2])
{
#pragma unroll 4
    for (int k = 0; k < K; k += 4) {
        float4 a0 = *(const float4*)(A + (ty*4+0)*AS + k);
        float4 a1 = *(const float4*)(A + (ty*4+1)*AS + k);
        float4 a2 = *(const float4*)(A + (ty*4+2)*AS + k);
        float4 a3 = *(const float4*)(A + (ty*4+3)*AS + k);
#pragma unroll
        for (int q = 0; q < 4; q++) {
            ulonglong2 b = *(const ulonglong2*)(B + (k+q)*BS + tx*4);
            uint64_t p0 = bcast2(getc(a0,q)), p1 = bcast2(getc(a1,q));
            uint64_t p2 = bcast2(getc(a2,q)), p3 = bcast2(getc(a3,q));
            acc[0][0] = ffma2(p0, b.x, acc[0][0]); acc[0][1] = ffma2(p0, b.y, acc[0][1]);
            acc[1][0] = ffma2(p1, b.x, acc[1][0]); acc[1][1] = ffma2(p1, b.y, acc[1][1]);
            acc[2][0] = ffma2(p2, b.x, acc[2][0]); acc[2][1] = ffma2(p2, b.y, acc[2][1]);
            acc[3][0] = ffma2(p3, b.x, acc[3][0]); acc[3][1] = ffma2(p3, b.y, acc[3][1]);
        }
    }
}
#define ZACC(a) { _Pragma("unroll") for (int _i=0;_i<4;_i++){ (a)[_i][0]=0ull; (a)[_i][1]=0ull; } }

// ---------------------------------------------------------------------------
// K1: per 64-row tile: s_enc, h, self_dyn -> g_SD, and AB projection -> g_AB
// ---------------------------------------------------------------------------
__global__ __launch_bounds__(256, 2)
void k1_kernel(const float* __restrict__ s,
               const float* __restrict__ W_enc,  const float* __restrict__ b_enc,
               const float* __restrict__ W_self0, const float* __restrict__ b_self0,
               const float* __restrict__ W_self1, const float* __restrict__ b_self1,
               const float* __restrict__ W_rel0,  const float* __restrict__ W_att0)
{
    extern __shared__ float sm[];
    float* SH = sm;               // 64*68  (s, then h)
    float* EN = sm + 4352;        // 64*68  (s_enc)
    float* WT = sm + 8704;        // 64*68
    float* BV = sm + 13056;       // 64

    const int tid = threadIdx.x;
    const int tx = tid & 15, ty = tid >> 4;
    const int row0 = blockIdx.x * 64;

    for (int idx = tid; idx < 4096; idx += 256) {
        int r = idx >> 6, c = idx & 63;
        SH[r*68+c] = s[(size_t)(row0 + r) * 64 + c];
        WT[r*68+c] = W_enc[idx];
    }
    if (tid < 64) BV[tid] = b_enc[tid];
    __syncthreads();

    uint64_t acc[4][2];

    // s_enc = concat(s[:2], (s@W_enc + b)[2:])
    ZACC(acc);
    tile_gemm2<64,68,68>(SH, WT, ty, tx, acc);
#pragma unroll
    for (int i = 0; i < 4; i++) {
        int r = ty*4 + i;
#pragma unroll
        for (int jp = 0; jp < 2; jp++) {
            float2 v = u2f(acc[i][jp]);
            int c = tx*4 + jp*2;
            float e0 = v.x + BV[c];     if (c     < 2) e0 = SH[r*68 + c];
            float e1 = v.y + BV[c + 1]; if (c + 1 < 2) e1 = SH[r*68 + c + 1];
            EN[r*68 + c]     = e0;
            EN[r*68 + c + 1] = e1;
        }
    }
    __syncthreads();

    // h = elu(s_enc @ W_self0 + b)
    for (int idx = tid; idx < 4096; idx += 256) WT[(idx>>6)*68 + (idx&63)] = W_self0[idx];
    if (tid < 64) BV[tid] = b_self0[tid];
    __syncthreads();
    ZACC(acc);
    tile_gemm2<64,68,68>(EN, WT, ty, tx, acc);
    __syncthreads();   // SH (s) dead after the s_enc stage; safe to overwrite with h
#pragma unroll
    for (int i = 0; i < 4; i++) {
        int r = ty*4 + i;
#pragma unroll
        for (int jp = 0; jp < 2; jp++) {
            float2 v = u2f(acc[i][jp]);
            int c = tx*4 + jp*2;
            SH[r*68 + c]     = eluf(v.x + BV[c]);
            SH[r*68 + c + 1] = eluf(v.y + BV[c + 1]);
        }
    }
    __syncthreads();

    // self_dyn = h @ W_self1 + b + h  -> g_SD
    for (int idx = tid; idx < 4096; idx += 256) WT[(idx>>6)*68 + (idx&63)] = W_self1[idx];
    if (tid < 64) BV[tid] = b_self1[tid];
    __syncthreads();
    ZACC(acc);
    tile_gemm2<64,68,68>(SH, WT, ty, tx, acc);
#pragma unroll
    for (int i = 0; i < 4; i++) {
        int r = ty*4 + i;
        float2 v0 = u2f(acc[i][0]), v1 = u2f(acc[i][1]);
        float4 v;
        v.x = v0.x + BV[tx*4+0] + SH[r*68 + tx*4+0];
        v.y = v0.y + BV[tx*4+1] + SH[r*68 + tx*4+1];
        v.z = v1.x + BV[tx*4+2] + SH[r*68 + tx*4+2];
        v.w = v1.y + BV[tx*4+3] + SH[r*68 + tx*4+3];
        *(float4*)&g_SD[(size_t)(row0 + r) * 64 + tx*4] = v;
    }

    // AB = s_enc @ [Wa_rel | Wb_rel | Wa_att | Wb_att]  (64 -> 512), 8 chunks
    for (int ch = 0; ch < 8; ch++) {
        __syncthreads();
        for (int idx = tid; idx < 4096; idx += 256) {
            int k = idx >> 6, c = idx & 63;
            int g = ch*64 + c;
            float w;
            if      (g < 128) w = W_rel0[k*128 + g];
            else if (g < 256) w = W_rel0[(64+k)*128 + (g-128)];
            else if (g < 384) w = W_att0[k*128 + (g-256)];
            else              w = W_att0[(64+k)*128 + (g-384)];
            WT[k*68+c] = w;
        }
        __syncthreads();
        ZACC(acc);
        tile_gemm2<64,68,68>(EN, WT, ty, tx, acc);
#pragma unroll
        for (int i = 0; i < 4; i++) {
            int r = ty*4 + i;
            ulonglong2 st;
            st.x = acc[i][0]; st.y = acc[i][1];   // bitwise = 4 floats
            *(ulonglong2*)&g_AB[(size_t)(row0 + r) * 512 + ch*64 + tx*4] = st;
        }
    }
}

// ---------------------------------------------------------------------------
// K2: pair phase, 512 threads. Warps 0-7: rel GEMM; warps 8-15: att GEMM.
// Fully parallel epilogue.
// ---------------------------------------------------------------------------
__global__ __launch_bounds__(512, 1)
void k2_kernel(const float* __restrict__ s,
               const float* __restrict__ W_rel0, const float* __restrict__ b_rel0,
               const float* __restrict__ W_rel1, const float* __restrict__ b_rel1,
               const float* __restrict__ W_rel2, const float* __restrict__ b_rel2,
               const float* __restrict__ W_att0, const float* __restrict__ b_att0,
               const float* __restrict__ W_att1, const float* __restrict__ b_att1,
               const float* __restrict__ W_att2, const float* __restrict__ b_att2,
               float* __restrict__ out)
{
    extern __shared__ float sm[];
    float* WR1 = sm;              // [128][68]
    float* WA1 = sm + 8704;       // [128][68]
    float* WR2 = sm + 17408;      // [64][64]
    float* XR  = sm + 21504;      // [64][132]
    float* XA  = sm + 29952;      // [64][132]
    float* HR  = sm + 38400;      // [64][68]
    float* HA  = sm + 42752;      // [64][68]
    float* ABs = sm + 47104;      // [8][512]
    float* wdr = sm + 51200;      // [128]
    float* b0r = sm + 51328;
    float* wda = sm + 51456;
    float* b0a = sm + 51584;
    float* b1r = sm + 51712;      // [64]
    float* b1a = sm + 51776;
    float* b2r = sm + 51840;
    float* w2a = sm + 51904;
    float* atp = sm + 51968;      // att  [64]
    float* zv  = sm + 52032;      // z    [64]
    float* psm = sm + 52096;      // pos  [16]
    float* zp  = sm + 52176;      // z partials [8][64]

    const int tid  = threadIdx.x;
    const int half = tid >> 8;    // 0: rel, 1: att
    const int t    = tid & 255;
    const int tx = t & 15, ty = t >> 4;

    for (int idx = tid; idx < 8192; idx += 512) {
        WR1[(idx>>6)*68 + (idx&63)] = W_rel1[idx];
        WA1[(idx>>6)*68 + (idx&63)] = W_att1[idx];
    }
    for (int idx = tid; idx < 4096; idx += 512) WR2[idx] = W_rel2[idx];
    if (tid < 128) {
        wdr[tid] = W_rel0[128*128 + tid];
        b0r[tid] = b_rel0[tid];
        wda[tid] = W_att0[128*128 + tid];
        b0a[tid] = b_att0[tid];
    }
    if (tid < 64) {
        b1r[tid] = b_rel1[tid];
        b1a[tid] = b_att1[tid];
        b2r[tid] = b_rel2[tid];
        w2a[tid] = W_att2[tid];
    }
    const float b2a = b_att2[0];
    __syncthreads();

    for (int bb = 0; bb < K2_BPB; bb++) {
        const int b = blockIdx.x * K2_BPB + bb;

        {
            const float4* src = (const float4*)(g_AB + (size_t)b * 4096);
            float4* dab = (float4*)ABs;
            for (int idx = tid; idx < 1024; idx += 512) dab[idx] = src[idx];
        }
        if (tid < 16) psm[tid] = s[(size_t)(b*8 + (tid>>1)) * 64 + (tid & 1)];
        __syncthreads();

        // build X_rel, X_att : elu(A_i + B_j + dist*Wd + b0), dist inlined
        for (int idx = tid; idx < 8192; idx += 512) {
            int p = idx >> 7, k = idx & 127;
            int i = p >> 3, j = p & 7;
            float dx = psm[2*i]   - psm[2*j];
            float dy = psm[2*i+1] - psm[2*j+1];
            float d = dx*dx + dy*dy;
            XR[p*132+k] = eluf(ABs[i*512 + k]       + ABs[j*512 + 128 + k] + d*wdr[k] + b0r[k]);
            XA[p*132+k] = eluf(ABs[i*512 + 256 + k] + ABs[j*512 + 384 + k] + d*wda[k] + b0a[k]);
        }
        __syncthreads();

        // rel_h2 = elu(X_rel @ W_rel1 + b1r)  [half 0]
        // att_h  = elu(X_att @ W_att1 + b1a)  [half 1]
        {
            const float* Xh = half ? XA  : XR;
            const float* Wh = half ? WA1 : WR1;
            float*       Hh = half ? HA  : HR;
            const float* bh = half ? b1a : b1r;
            uint64_t acc[4][2]; ZACC(acc);
            tile_gemm2<128,132,68>(Xh, Wh, ty, tx, acc);
#pragma unroll
            for (int i2 = 0; i2 < 4; i2++) {
                int r = ty*4 + i2;
#pragma unroll
                for (int jp = 0; jp < 2; jp++) {
                    float2 v = u2f(acc[i2][jp]);
                    int c = tx*4 + jp*2;
                    Hh[r*68 + c]     = eluf(v.x + bh[c]);
                    Hh[r*68 + c + 1] = eluf(v.y + bh[c + 1]);
                }
            }
        }
        __syncthreads();

        // att[p] = sigmoid(att_h[p].w2a + b2a), diag-masked — 8 lanes per pair
        {
            int p = tid >> 3, u = tid & 7;
            float a = 0.f;
#pragma unroll
            for (int m = 0; m < 8; m++) a = fmaf(HA[p*68 + u*8 + m], w2a[u*8 + m], a);
            a += __shfl_xor_sync(0xffffffffu, a, 1);
            a += __shfl_xor_sync(0xffffffffu, a, 2);
            a += __shfl_xor_sync(0xffffffffu, a, 4);
            if (u == 0) {
                a += b2a;
                int i = p >> 3, j = p & 7;
                atp[p] = (i == j) ? 0.f : 1.f / (1.f + __expf(-a));
            }
        }
        __syncthreads();

        // z partials: 8 p-groups x 64 channels
        {
            int c = tid & 63, g = tid >> 6;
            float zc = 0.f;
#pragma unroll
            for (int m = 0; m < 8; m++) zc = fmaf(atp[g*8 + m], HR[(g*8 + m)*68 + c], zc);
            zp[g*64 + c] = zc;
        }
        __syncthreads();

        if (tid < 64) {
            float zc = 0.f;
#pragma unroll
            for (int g = 0; g < 8; g++) zc += zp[g*64 + tid];
            zv[tid] = zc;
        }
        __syncthreads();

        // out = sum_i sd + z + a0*b_rel2 + z @ W_rel2
        if (tid < 64) {
            float a0 = 0.f;
#pragma unroll
            for (int p = 0; p < 64; p++) a0 += atp[p];
            float o = zv[tid] + a0 * b2r[tid];
#pragma unroll
            for (int k = 0; k < 64; k++) o = fmaf(zv[k], WR2[k*64 + tid], o);
#pragma unroll
            for (int i = 0; i < 8; i++) o += g_SD[(size_t)(b*8 + i) * 64 + tid];
            out[(size_t)b * 64 + tid] = o;
        }
        __syncthreads();
    }
}

// ---------------------------------------------------------------------------
extern "C" void kernel_launch(void* const* d_in, const int* in_sizes, int n_in,
                              void* d_out, int out_size)
{
    const float* s       = (const float*)d_in[0];
    const float* W_enc   = (const float*)d_in[1];
    const float* b_enc   = (const float*)d_in[2];
    const float* W_self0 = (const float*)d_in[3];
    const float* b_self0 = (const float*)d_in[4];
    const float* W_self1 = (const float*)d_in[5];
    const float* b_self1 = (const float*)d_in[6];
    const float* W_rel0  = (const float*)d_in[7];
    const float* b_rel0  = (const float*)d_in[8];
    const float* W_rel1  = (const float*)d_in[9];
    const float* b_rel1  = (const float*)d_in[10];
    const float* W_rel2  = (const float*)d_in[11];
    const float* b_rel2  = (const float*)d_in[12];
    const float* W_att0  = (const float*)d_in[13];
    const float* b_att0  = (const float*)d_in[14];
    const float* W_att1  = (const float*)d_in[15];
    const float* b_att1  = (const float*)d_in[16];
    const float* W_att2  = (const float*)d_in[17];
    const float* b_att2  = (const float*)d_in[18];
    float* out = (float*)d_out;

    const int smem1 = 13120 * 4;           // 52,480 B
    const int smem2 = (52176 + 512) * 4;   // 210,752 B
    cudaFuncSetAttribute(k1_kernel, cudaFuncAttributeMaxDynamicSharedMemorySize, smem1);
    cudaFuncSetAttribute(k2_kernel, cudaFuncAttributeMaxDynamicSharedMemorySize, smem2);

    k1_kernel<<<ROWS/64, 256, smem1>>>(s, W_enc, b_enc, W_self0, b_self0,
                                       W_self1, b_self1, W_rel0, W_att0);
    k2_kernel<<<BATCH/K2_BPB, 512, smem2>>>(s, W_rel0, b_rel0, W_rel1, b_rel1,
                                            W_rel2, b_rel2, W_att0, b_att0,
                                            W_att1, b_att1, W_att2, b_att2, out);
}

// round 5
// speedup vs baseline: 1.3836x; 1.1898x over previous
#include <cuda_runtime.h>
#include <stdint.h>
#include <math.h>

#define BATCH 8192
#define ROWS  65536

// Scratch (static device globals; allocation-free per harness rules)
__device__ float g_AB[(size_t)ROWS * 512];  // per row: [A_rel(128)|B_rel(128)|A_att(128)|B_att(128)]
__device__ float g_SD[(size_t)ROWS * 64];   // self_dyn per (b,i)

__device__ __forceinline__ float eluf(float x) {
    return x > 0.f ? x : (__expf(x) - 1.f);
}
__device__ __forceinline__ uint64_t ffma2(uint64_t a, uint64_t b, uint64_t c) {
    uint64_t d;
    asm("fma.rn.f32x2 %0, %1, %2, %3;" : "=l"(d) : "l"(a), "l"(b), "l"(c));
    return d;
}
__device__ __forceinline__ uint64_t bcast2(float v) {
    uint64_t d;
    asm("mov.b64 %0, {%1, %1};" : "=l"(d) : "f"(v));
    return d;
}
__device__ __forceinline__ float2 u2f(uint64_t u) {
    float2 f;
    asm("mov.b64 {%0, %1}, %2;" : "=f"(f.x), "=f"(f.y) : "l"(u));
    return f;
}
__device__ __forceinline__ float getc(const float4& v, int q) {
    return q == 0 ? v.x : q == 1 ? v.y : q == 2 ? v.z : v.w;
}

template<int K, int AS, int BS>
__device__ __forceinline__ void tile_gemm2(const float* __restrict__ A,
                                           const float* __restrict__ B,
                                           int ty, int tx, uint64_t acc[4][2])
{
#pragma unroll 4
    for (int k = 0; k < K; k += 4) {
        float4 a0 = *(const float4*)(A + (ty*4+0)*AS + k);
        float4 a1 = *(const float4*)(A + (ty*4+1)*AS + k);
        float4 a2 = *(const float4*)(A + (ty*4+2)*AS + k);
        float4 a3 = *(const float4*)(A + (ty*4+3)*AS + k);
#pragma unroll
        for (int q = 0; q < 4; q++) {
            ulonglong2 b = *(const ulonglong2*)(B + (k+q)*BS + tx*4);
            uint64_t p0 = bcast2(getc(a0,q)), p1 = bcast2(getc(a1,q));
            uint64_t p2 = bcast2(getc(a2,q)), p3 = bcast2(getc(a3,q));
            acc[0][0] = ffma2(p0, b.x, acc[0][0]); acc[0][1] = ffma2(p0, b.y, acc[0][1]);
            acc[1][0] = ffma2(p1, b.x, acc[1][0]); acc[1][1] = ffma2(p1, b.y, acc[1][1]);
            acc[2][0] = ffma2(p2, b.x, acc[2][0]); acc[2][1] = ffma2(p2, b.y, acc[2][1]);
            acc[3][0] = ffma2(p3, b.x, acc[3][0]); acc[3][1] = ffma2(p3, b.y, acc[3][1]);
        }
    }
}
#define ZACC(a) { _Pragma("unroll") for (int _i=0;_i<4;_i++){ (a)[_i][0]=0ull; (a)[_i][1]=0ull; } }

// ---------------------------------------------------------------------------
// K1: unchanged (per 64-row tile: s_enc, h, self_dyn, AB projection)
// ---------------------------------------------------------------------------
__global__ __launch_bounds__(256, 2)
void k1_kernel(const float* __restrict__ s,
               const float* __restrict__ W_enc,  const float* __restrict__ b_enc,
               const float* __restrict__ W_self0, const float* __restrict__ b_self0,
               const float* __restrict__ W_self1, const float* __restrict__ b_self1,
               const float* __restrict__ W_rel0,  const float* __restrict__ W_att0)
{
    extern __shared__ float sm[];
    float* SH = sm;
    float* EN = sm + 4352;
    float* WT = sm + 8704;
    float* BV = sm + 13056;

    const int tid = threadIdx.x;
    const int tx = tid & 15, ty = tid >> 4;
    const int row0 = blockIdx.x * 64;

    for (int idx = tid; idx < 4096; idx += 256) {
        int r = idx >> 6, c = idx & 63;
        SH[r*68+c] = s[(size_t)(row0 + r) * 64 + c];
        WT[r*68+c] = W_enc[idx];
    }
    if (tid < 64) BV[tid] = b_enc[tid];
    __syncthreads();

    uint64_t acc[4][2];

    ZACC(acc);
    tile_gemm2<64,68,68>(SH, WT, ty, tx, acc);
#pragma unroll
    for (int i = 0; i < 4; i++) {
        int r = ty*4 + i;
#pragma unroll
        for (int jp = 0; jp < 2; jp++) {
            float2 v = u2f(acc[i][jp]);
            int c = tx*4 + jp*2;
            float e0 = v.x + BV[c];     if (c     < 2) e0 = SH[r*68 + c];
            float e1 = v.y + BV[c + 1]; if (c + 1 < 2) e1 = SH[r*68 + c + 1];
            EN[r*68 + c]     = e0;
            EN[r*68 + c + 1] = e1;
        }
    }
    __syncthreads();

    for (int idx = tid; idx < 4096; idx += 256) WT[(idx>>6)*68 + (idx&63)] = W_self0[idx];
    if (tid < 64) BV[tid] = b_self0[tid];
    __syncthreads();
    ZACC(acc);
    tile_gemm2<64,68,68>(EN, WT, ty, tx, acc);
    __syncthreads();
#pragma unroll
    for (int i = 0; i < 4; i++) {
        int r = ty*4 + i;
#pragma unroll
        for (int jp = 0; jp < 2; jp++) {
            float2 v = u2f(acc[i][jp]);
            int c = tx*4 + jp*2;
            SH[r*68 + c]     = eluf(v.x + BV[c]);
            SH[r*68 + c + 1] = eluf(v.y + BV[c + 1]);
        }
    }
    __syncthreads();

    for (int idx = tid; idx < 4096; idx += 256) WT[(idx>>6)*68 + (idx&63)] = W_self1[idx];
    if (tid < 64) BV[tid] = b_self1[tid];
    __syncthreads();
    ZACC(acc);
    tile_gemm2<64,68,68>(SH, WT, ty, tx, acc);
#pragma unroll
    for (int i = 0; i < 4; i++) {
        int r = ty*4 + i;
        float2 v0 = u2f(acc[i][0]), v1 = u2f(acc[i][1]);
        float4 v;
        v.x = v0.x + BV[tx*4+0] + SH[r*68 + tx*4+0];
        v.y = v0.y + BV[tx*4+1] + SH[r*68 + tx*4+1];
        v.z = v1.x + BV[tx*4+2] + SH[r*68 + tx*4+2];
        v.w = v1.y + BV[tx*4+3] + SH[r*68 + tx*4+3];
        *(float4*)&g_SD[(size_t)(row0 + r) * 64 + tx*4] = v;
    }

    for (int ch = 0; ch < 8; ch++) {
        __syncthreads();
        for (int idx = tid; idx < 4096; idx += 256) {
            int k = idx >> 6, c = idx & 63;
            int g = ch*64 + c;
            float w;
            if      (g < 128) w = W_rel0[k*128 + g];
            else if (g < 256) w = W_rel0[(64+k)*128 + (g-128)];
            else if (g < 384) w = W_att0[k*128 + (g-256)];
            else              w = W_att0[(64+k)*128 + (g-384)];
            WT[k*68+c] = w;
        }
        __syncthreads();
        ZACC(acc);
        tile_gemm2<64,68,68>(EN, WT, ty, tx, acc);
#pragma unroll
        for (int i = 0; i < 4; i++) {
            int r = ty*4 + i;
            ulonglong2 st;
            st.x = acc[i][0]; st.y = acc[i][1];
            *(ulonglong2*)&g_AB[(size_t)(row0 + r) * 512 + ch*64 + tx*4] = st;
        }
    }
}

// ===========================================================================
// K2: pair phase with mma.sync bf16 hi/lo (3-product). 512 threads.
// Warps 0-7: rel GEMM; warps 8-15: att GEMM. R2-proven epilogue.
// ===========================================================================
// smem byte offsets; X/W rows padded to 136 bf16 (272 B) for conflict-free ldmatrix
#define SKX      136
#define SM_XRHI  0
#define SM_XRLO  17408
#define SM_XAHI  34816
#define SM_XALO  52224
#define SM_WRHI  69632
#define SM_WRLO  87040
#define SM_WAHI  104448
#define SM_WALO  121856
#define SM_HR    139264
#define SM_HA    156672
#define SM_WR2   174080
#define SM_B1R   190464
#define SM_B1A   190720
#define SM_B2R   190976
#define SM_W2A   191232
#define SM_PSM   191488
#define SM_ATP   191616
#define SM_ZVV   191872
#define SM_ZP    192128
#define SM_ABS   194176
#define SMEM2_BYTES 210560

__device__ __forceinline__ uint32_t smem_u32(const void* p) {
    uint32_t a;
    asm("{ .reg .u64 t; cvta.to.shared.u64 t, %1; cvt.u32.u64 %0, t; }" : "=r"(a) : "l"(p));
    return a;
}
// split x0,x1 (memory order: x0 first) into packed bf16 hi pair + lo pair
__device__ __forceinline__ void split2(float x0, float x1, uint32_t& hi, uint32_t& lo) {
    uint32_t h;
    asm("cvt.rn.bf16x2.f32 %0, %1, %2;" : "=r"(h) : "f"(x1), "f"(x0));
    float h0 = __uint_as_float(h << 16);
    float h1 = __uint_as_float(h & 0xffff0000u);
    float l0 = x0 - h0, l1 = x1 - h1;
    uint32_t l;
    asm("cvt.rn.bf16x2.f32 %0, %1, %2;" : "=r"(l) : "f"(l1), "f"(l0));
    hi = h; lo = l;
}
__device__ __forceinline__ void ldsm4(uint32_t r[4], uint32_t addr) {
    asm volatile("ldmatrix.sync.aligned.m8n8.x4.shared.b16 {%0,%1,%2,%3}, [%4];"
        : "=r"(r[0]), "=r"(r[1]), "=r"(r[2]), "=r"(r[3]) : "r"(addr));
}
__device__ __forceinline__ void mma16816(float d[4], const uint32_t a[4],
                                         uint32_t b0, uint32_t b1) {
    asm volatile("mma.sync.aligned.m16n8k16.row.col.f32.bf16.bf16.f32 "
        "{%0,%1,%2,%3}, {%4,%5,%6,%7}, {%8,%9}, {%0,%1,%2,%3};"
        : "+f"(d[0]), "+f"(d[1]), "+f"(d[2]), "+f"(d[3])
        : "r"(a[0]), "r"(a[1]), "r"(a[2]), "r"(a[3]), "r"(b0), "r"(b1));
}

__global__ __launch_bounds__(512, 1)
void k2_kernel(const float* __restrict__ s,
               const float* __restrict__ W_rel0, const float* __restrict__ b_rel0,
               const float* __restrict__ W_rel1, const float* __restrict__ b_rel1,
               const float* __restrict__ W_rel2, const float* __restrict__ b_rel2,
               const float* __restrict__ W_att0, const float* __restrict__ b_att0,
               const float* __restrict__ W_att1, const float* __restrict__ b_att1,
               const float* __restrict__ W_att2, const float* __restrict__ b_att2,
               float* __restrict__ out)
{
    extern __shared__ char smc[];
    const int tid  = threadIdx.x;
    const int wid  = tid >> 5;
    const int lane = tid & 31;
    const uint32_t smb = smem_u32(smc);

    float* HR    = (float*)(smc + SM_HR);    // [64][68]
    float* HA    = (float*)(smc + SM_HA);
    float* wr2_s = (float*)(smc + SM_WR2);
    float* b1r_s = (float*)(smc + SM_B1R);
    float* b1a_s = (float*)(smc + SM_B1A);
    float* b2r_s = (float*)(smc + SM_B2R);
    float* w2a_s = (float*)(smc + SM_W2A);
    float* psm   = (float*)(smc + SM_PSM);
    float* atp   = (float*)(smc + SM_ATP);
    float* zv    = (float*)(smc + SM_ZVV);
    float* zp    = (float*)(smc + SM_ZP);
    float* ABs   = (float*)(smc + SM_ABS);

    // ---- one-time staging: W tiles bf16 hi/lo, [n=64][k padded 136] ----
    for (int idx = tid; idx < 4096; idx += 512) {
        int n = idx >> 6;
        int kp = (idx & 63) * 2;
        uint32_t off = (uint32_t)(n * 272 + kp * 2);
        uint32_t h, l;
        split2(W_rel1[kp*64 + n], W_rel1[(kp+1)*64 + n], h, l);
        *(uint32_t*)(smc + SM_WRHI + off) = h;
        *(uint32_t*)(smc + SM_WRLO + off) = l;
        split2(W_att1[kp*64 + n], W_att1[(kp+1)*64 + n], h, l);
        *(uint32_t*)(smc + SM_WAHI + off) = h;
        *(uint32_t*)(smc + SM_WALO + off) = l;
    }
    for (int idx = tid; idx < 4096; idx += 512) wr2_s[idx] = W_rel2[idx];
    if (tid < 64) {
        b1r_s[tid] = b_rel1[tid];
        b1a_s[tid] = b_att1[tid];
        b2r_s[tid] = b_rel2[tid];
        w2a_s[tid] = W_att2[tid];
    }
    const float b2a = b_att2[0];

    // per-thread X-build constants (4 consecutive k per thread-iter)
    // idx in [0,2048): p = idx>>5, k0 = (idx&31)*4
    // per-warp GEMM constants
    const int half = wid >> 3;          // 0 rel, 1 att
    const int wg = wid & 7;
    const int wm = wg & 3;              // M-tile (16 rows)
    const int wn = wg >> 1 >> 1;        // wn = wg>>2 : N-half (32 cols)
    const uint32_t xhi_base = smb + (half ? SM_XAHI : SM_XRHI);
    const uint32_t xlo_base = smb + (half ? SM_XALO : SM_XRLO);
    const uint32_t whi_base = smb + (half ? SM_WAHI : SM_WRHI);
    const uint32_t wlo_base = smb + (half ? SM_WALO : SM_WRLO);
    const uint32_t aoff = (uint32_t)((wm*16 + (lane & 15)) * 272 + ((lane >> 4) * 8) * 2);
    // B addr for n-tile pair q: lanes 0-7 (n0-7,k0) | 8-15 (n0-7,k8) | 16-23 (n8-15,k0) | 24-31 (n8-15,k8)
    const int bn_q0 = wn*32 + (lane & 7) + ((lane >> 4) << 3);
    const int bkoff = ((lane >> 3) & 1) * 8;
    const uint32_t boff0 = (uint32_t)(bn_q0 * 272 + bkoff * 2);
    const uint32_t boff1 = boff0 + 16 * 272;

    __syncthreads();

    for (int bb = 0; bb < 8; bb++) {
        const int b = blockIdx.x * 8 + bb;

        {
            const float4* src = (const float4*)(g_AB + (size_t)b * 4096);
            float4* dab = (float4*)ABs;
            for (int idx = tid; idx < 1024; idx += 512) dab[idx] = src[idx];
        }
        if (tid < 16) psm[tid] = s[(size_t)(b*8 + (tid>>1)) * 64 + (tid & 1)];
        __syncthreads();

        // ---- build X tiles as bf16 hi/lo ----
        for (int idx = tid; idx < 2048; idx += 512) {
            const int p = idx >> 5, k0 = (idx & 31) * 4;
            const int i = p >> 3, j = p & 7;
            const float dx = psm[2*i]   - psm[2*j];
            const float dy = psm[2*i+1] - psm[2*j+1];
            const float d = dx*dx + dy*dy;
            const uint32_t off = (uint32_t)(p * 272 + k0 * 2);

            float4 Ar = *(const float4*)&ABs[i*512 + k0];
            float4 Br = *(const float4*)&ABs[j*512 + 128 + k0];
            float4 wd = *(const float4*)&W_rel0[128*128 + k0];
            float4 b0 = *(const float4*)&b_rel0[k0];
            float x0 = eluf(Ar.x + Br.x + fmaf(d, wd.x, b0.x));
            float x1 = eluf(Ar.y + Br.y + fmaf(d, wd.y, b0.y));
            float x2 = eluf(Ar.z + Br.z + fmaf(d, wd.z, b0.z));
            float x3 = eluf(Ar.w + Br.w + fmaf(d, wd.w, b0.w));
            uint32_t h0, l0, h1, l1;
            split2(x0, x1, h0, l0);
            split2(x2, x3, h1, l1);
            *(uint2*)(smc + SM_XRHI + off) = make_uint2(h0, h1);
            *(uint2*)(smc + SM_XRLO + off) = make_uint2(l0, l1);

            Ar = *(const float4*)&ABs[i*512 + 256 + k0];
            Br = *(const float4*)&ABs[j*512 + 384 + k0];
            wd = *(const float4*)&W_att0[128*128 + k0];
            b0 = *(const float4*)&b_att0[k0];
            x0 = eluf(Ar.x + Br.x + fmaf(d, wd.x, b0.x));
            x1 = eluf(Ar.y + Br.y + fmaf(d, wd.y, b0.y));
            x2 = eluf(Ar.z + Br.z + fmaf(d, wd.z, b0.z));
            x3 = eluf(Ar.w + Br.w + fmaf(d, wd.w, b0.w));
            split2(x0, x1, h0, l0);
            split2(x2, x3, h1, l1);
            *(uint2*)(smc + SM_XAHI + off) = make_uint2(h0, h1);
            *(uint2*)(smc + SM_XALO + off) = make_uint2(l0, l1);
        }
        __syncthreads();

        // ---- warp GEMM: 16x32 tile, 8 k-steps, hi/lo 3-product ----
        {
            float d0[4] = {0,0,0,0}, d1[4] = {0,0,0,0}, d2[4] = {0,0,0,0}, d3[4] = {0,0,0,0};
            uint32_t aH = xhi_base + aoff, aL = xlo_base + aoff;
            uint32_t bH0 = whi_base + boff0, bH1 = whi_base + boff1;
            uint32_t bL0 = wlo_base + boff0, bL1 = wlo_base + boff1;
#pragma unroll
            for (int ks = 0; ks < 8; ks++) {
                uint32_t ah[4], al[4], bh0[4], bh1[4], bl0[4], bl1[4];
                ldsm4(ah, aH);  ldsm4(al, aL);
                ldsm4(bh0, bH0); ldsm4(bh1, bH1);
                ldsm4(bl0, bL0); ldsm4(bl1, bL1);
                aH += 32; aL += 32; bH0 += 32; bH1 += 32; bL0 += 32; bL1 += 32;

                mma16816(d0, ah, bh0[0], bh0[1]);
                mma16816(d1, ah, bh0[2], bh0[3]);
                mma16816(d2, ah, bh1[0], bh1[1]);
                mma16816(d3, ah, bh1[2], bh1[3]);
                mma16816(d0, ah, bl0[0], bl0[1]);
                mma16816(d1, ah, bl0[2], bl0[3]);
                mma16816(d2, ah, bl1[0], bl1[1]);
                mma16816(d3, ah, bl1[2], bl1[3]);
                mma16816(d0, al, bh0[0], bh0[1]);
                mma16816(d1, al, bh0[2], bh0[3]);
                mma16816(d2, al, bh1[0], bh1[1]);
                mma16816(d3, al, bh1[2], bh1[3]);
            }
            // store elu(D + bias) to H
            float* Hh = half ? HA : HR;
            const float* bias = half ? b1a_s : b1r_s;
            const int r0 = wm*16 + (lane >> 2);
            const int cb = wn*32 + (lane & 3)*2;
#pragma unroll
            for (int nt = 0; nt < 4; nt++) {
                const float* dn = nt == 0 ? d0 : nt == 1 ? d1 : nt == 2 ? d2 : d3;
                const int c = cb + nt*8;
                Hh[r0*68 + c]       = eluf(dn[0] + bias[c]);
                Hh[r0*68 + c + 1]   = eluf(dn[1] + bias[c+1]);
                Hh[(r0+8)*68 + c]   = eluf(dn[2] + bias[c]);
                Hh[(r0+8)*68 + c+1] = eluf(dn[3] + bias[c+1]);
            }
        }
        __syncthreads();

        // att[p] = sigmoid(att_h[p].w2a + b2a), diag-masked — 8 lanes per pair
        {
            int p = tid >> 3, u = tid & 7;
            float a = 0.f;
#pragma unroll
            for (int m = 0; m < 8; m++) a = fmaf(HA[p*68 + u*8 + m], w2a_s[u*8 + m], a);
            a += __shfl_xor_sync(0xffffffffu, a, 1);
            a += __shfl_xor_sync(0xffffffffu, a, 2);
            a += __shfl_xor_sync(0xffffffffu, a, 4);
            if (u == 0) {
                a += b2a;
                int i = p >> 3, j = p & 7;
                atp[p] = (i == j) ? 0.f : 1.f / (1.f + __expf(-a));
            }
        }
        __syncthreads();

        // z partials: 8 p-groups x 64 channels
        {
            int c = tid & 63, g = tid >> 6;
            float zc = 0.f;
#pragma unroll
            for (int m = 0; m < 8; m++) zc = fmaf(atp[g*8 + m], HR[(g*8 + m)*68 + c], zc);
            zp[g*64 + c] = zc;
        }
        __syncthreads();

        if (tid < 64) {
            float zc = 0.f;
#pragma unroll
            for (int g = 0; g < 8; g++) zc += zp[g*64 + tid];
            zv[tid] = zc;
        }
        __syncthreads();

        // out = sum_i sd + z + a0*b_rel2 + z @ W_rel2
        if (tid < 64) {
            float a0 = 0.f;
#pragma unroll
            for (int p = 0; p < 64; p++) a0 += atp[p];
            float o = zv[tid] + a0 * b2r_s[tid];
#pragma unroll
            for (int k = 0; k < 64; k++) o = fmaf(zv[k], wr2_s[k*64 + tid], o);
#pragma unroll
            for (int i = 0; i < 8; i++) o += g_SD[(size_t)(b*8 + i) * 64 + tid];
            out[(size_t)b * 64 + tid] = o;
        }
        __syncthreads();
    }
}

// ---------------------------------------------------------------------------
extern "C" void kernel_launch(void* const* d_in, const int* in_sizes, int n_in,
                              void* d_out, int out_size)
{
    const float* s       = (const float*)d_in[0];
    const float* W_enc   = (const float*)d_in[1];
    const float* b_enc   = (const float*)d_in[2];
    const float* W_self0 = (const float*)d_in[3];
    const float* b_self0 = (const float*)d_in[4];
    const float* W_self1 = (const float*)d_in[5];
    const float* b_self1 = (const float*)d_in[6];
    const float* W_rel0  = (const float*)d_in[7];
    const float* b_rel0  = (const float*)d_in[8];
    const float* W_rel1  = (const float*)d_in[9];
    const float* b_rel1  = (const float*)d_in[10];
    const float* W_rel2  = (const float*)d_in[11];
    const float* b_rel2  = (const float*)d_in[12];
    const float* W_att0  = (const float*)d_in[13];
    const float* b_att0  = (const float*)d_in[14];
    const float* W_att1  = (const float*)d_in[15];
    const float* b_att1  = (const float*)d_in[16];
    const float* W_att2  = (const float*)d_in[17];
    const float* b_att2  = (const float*)d_in[18];
    float* out = (float*)d_out;

    const int smem1 = 13120 * 4;
    cudaFuncSetAttribute(k1_kernel, cudaFuncAttributeMaxDynamicSharedMemorySize, smem1);
    cudaFuncSetAttribute(k2_kernel, cudaFuncAttributeMaxDynamicSharedMemorySize, SMEM2_BYTES);

    k1_kernel<<<ROWS/64, 256, smem1>>>(s, W_enc, b_enc, W_self0, b_self0,
                                       W_self1, b_self1, W_rel0, W_att0);
    k2_kernel<<<BATCH/8, 512, SMEM2_BYTES>>>(s, W_rel0, b_rel0, W_rel1, b_rel1,
                                             W_rel2, b_rel2, W_att0, b_att0,
                                             W_att1, b_att1, W_att2, b_att2, out);
}

// round 7
// speedup vs baseline: 1.8596x; 1.3441x over previous
#include <cuda_runtime.h>
#include <stdint.h>
#include <math.h>

#define BATCH 8192
#define ROWS  65536

// Scratch (static device globals; allocation-free per harness rules)
__device__ float g_AB[(size_t)ROWS * 512];  // per row: [A_rel(128)|B_rel(128)|A_att(128)|B_att(128)]
__device__ float g_SD[(size_t)ROWS * 64];   // self_dyn per (b,i)

__device__ __forceinline__ float eluf(float x) {
    return x > 0.f ? x : (__expf(x) - 1.f);
}
__device__ __forceinline__ uint64_t ffma2(uint64_t a, uint64_t b, uint64_t c) {
    uint64_t d;
    asm("fma.rn.f32x2 %0, %1, %2, %3;" : "=l"(d) : "l"(a), "l"(b), "l"(c));
    return d;
}
__device__ __forceinline__ uint64_t bcast2(float v) {
    uint64_t d;
    asm("mov.b64 %0, {%1, %1};" : "=l"(d) : "f"(v));
    return d;
}
__device__ __forceinline__ float2 u2f(uint64_t u) {
    float2 f;
    asm("mov.b64 {%0, %1}, %2;" : "=f"(f.x), "=f"(f.y) : "l"(u));
    return f;
}
__device__ __forceinline__ float getc(const float4& v, int q) {
    return q == 0 ? v.x : q == 1 ? v.y : q == 2 ? v.z : v.w;
}

template<int K, int AS, int BS>
__device__ __forceinline__ void tile_gemm2(const float* __restrict__ A,
                                           const float* __restrict__ B,
                                           int ty, int tx, uint64_t acc[4][2])
{
#pragma unroll 4
    for (int k = 0; k < K; k += 4) {
        float4 a0 = *(const float4*)(A + (ty*4+0)*AS + k);
        float4 a1 = *(const float4*)(A + (ty*4+1)*AS + k);
        float4 a2 = *(const float4*)(A + (ty*4+2)*AS + k);
        float4 a3 = *(const float4*)(A + (ty*4+3)*AS + k);
#pragma unroll
        for (int q = 0; q < 4; q++) {
            ulonglong2 b = *(const ulonglong2*)(B + (k+q)*BS + tx*4);
            uint64_t p0 = bcast2(getc(a0,q)), p1 = bcast2(getc(a1,q));
            uint64_t p2 = bcast2(getc(a2,q)), p3 = bcast2(getc(a3,q));
            acc[0][0] = ffma2(p0, b.x, acc[0][0]); acc[0][1] = ffma2(p0, b.y, acc[0][1]);
            acc[1][0] = ffma2(p1, b.x, acc[1][0]); acc[1][1] = ffma2(p1, b.y, acc[1][1]);
            acc[2][0] = ffma2(p2, b.x, acc[2][0]); acc[2][1] = ffma2(p2, b.y, acc[2][1]);
            acc[3][0] = ffma2(p3, b.x, acc[3][0]); acc[3][1] = ffma2(p3, b.y, acc[3][1]);
        }
    }
}
#define ZACC(a) { _Pragma("unroll") for (int _i=0;_i<4;_i++){ (a)[_i][0]=0ull; (a)[_i][1]=0ull; } }

// ---------------------------------------------------------------------------
// K1: unchanged (per 64-row tile: s_enc, h, self_dyn, AB projection)
// ---------------------------------------------------------------------------
__global__ __launch_bounds__(256, 2)
void k1_kernel(const float* __restrict__ s,
               const float* __restrict__ W_enc,  const float* __restrict__ b_enc,
               const float* __restrict__ W_self0, const float* __restrict__ b_self0,
               const float* __restrict__ W_self1, const float* __restrict__ b_self1,
               const float* __restrict__ W_rel0,  const float* __restrict__ W_att0)
{
    extern __shared__ float sm[];
    float* SH = sm;
    float* EN = sm + 4352;
    float* WT = sm + 8704;
    float* BV = sm + 13056;

    const int tid = threadIdx.x;
    const int tx = tid & 15, ty = tid >> 4;
    const int row0 = blockIdx.x * 64;

    for (int idx = tid; idx < 4096; idx += 256) {
        int r = idx >> 6, c = idx & 63;
        SH[r*68+c] = s[(size_t)(row0 + r) * 64 + c];
        WT[r*68+c] = W_enc[idx];
    }
    if (tid < 64) BV[tid] = b_enc[tid];
    __syncthreads();

    uint64_t acc[4][2];

    ZACC(acc);
    tile_gemm2<64,68,68>(SH, WT, ty, tx, acc);
#pragma unroll
    for (int i = 0; i < 4; i++) {
        int r = ty*4 + i;
#pragma unroll
        for (int jp = 0; jp < 2; jp++) {
            float2 v = u2f(acc[i][jp]);
            int c = tx*4 + jp*2;
            float e0 = v.x + BV[c];     if (c     < 2) e0 = SH[r*68 + c];
            float e1 = v.y + BV[c + 1]; if (c + 1 < 2) e1 = SH[r*68 + c + 1];
            EN[r*68 + c]     = e0;
            EN[r*68 + c + 1] = e1;
        }
    }
    __syncthreads();

    for (int idx = tid; idx < 4096; idx += 256) WT[(idx>>6)*68 + (idx&63)] = W_self0[idx];
    if (tid < 64) BV[tid] = b_self0[tid];
    __syncthreads();
    ZACC(acc);
    tile_gemm2<64,68,68>(EN, WT, ty, tx, acc);
    __syncthreads();
#pragma unroll
    for (int i = 0; i < 4; i++) {
        int r = ty*4 + i;
#pragma unroll
        for (int jp = 0; jp < 2; jp++) {
            float2 v = u2f(acc[i][jp]);
            int c = tx*4 + jp*2;
            SH[r*68 + c]     = eluf(v.x + BV[c]);
            SH[r*68 + c + 1] = eluf(v.y + BV[c + 1]);
        }
    }
    __syncthreads();

    for (int idx = tid; idx < 4096; idx += 256) WT[(idx>>6)*68 + (idx&63)] = W_self1[idx];
    if (tid < 64) BV[tid] = b_self1[tid];
    __syncthreads();
    ZACC(acc);
    tile_gemm2<64,68,68>(SH, WT, ty, tx, acc);
#pragma unroll
    for (int i = 0; i < 4; i++) {
        int r = ty*4 + i;
        float2 v0 = u2f(acc[i][0]), v1 = u2f(acc[i][1]);
        float4 v;
        v.x = v0.x + BV[tx*4+0] + SH[r*68 + tx*4+0];
        v.y = v0.y + BV[tx*4+1] + SH[r*68 + tx*4+1];
        v.z = v1.x + BV[tx*4+2] + SH[r*68 + tx*4+2];
        v.w = v1.y + BV[tx*4+3] + SH[r*68 + tx*4+3];
        *(float4*)&g_SD[(size_t)(row0 + r) * 64 + tx*4] = v;
    }

    for (int ch = 0; ch < 8; ch++) {
        __syncthreads();
        for (int idx = tid; idx < 4096; idx += 256) {
            int k = idx >> 6, c = idx & 63;
            int g = ch*64 + c;
            float w;
            if      (g < 128) w = W_rel0[k*128 + g];
            else if (g < 256) w = W_rel0[(64+k)*128 + (g-128)];
            else if (g < 384) w = W_att0[k*128 + (g-256)];
            else              w = W_att0[(64+k)*128 + (g-384)];
            WT[k*68+c] = w;
        }
        __syncthreads();
        ZACC(acc);
        tile_gemm2<64,68,68>(EN, WT, ty, tx, acc);
#pragma unroll
        for (int i = 0; i < 4; i++) {
            int r = ty*4 + i;
            ulonglong2 st;
            st.x = acc[i][0]; st.y = acc[i][1];
            *(ulonglong2*)&g_AB[(size_t)(row0 + r) * 512 + ch*64 + tx*4] = st;
        }
    }
}

// ===========================================================================
// K2: pair phase, mma.sync bf16 hi/lo, supersteps of 2 batches (M=128),
// B-hi fragments hoisted to registers, register epilogue, pipelined ABs.
// ===========================================================================
#define SM_XRHI  0
#define SM_XRLO  34816
#define SM_XAHI  69632
#define SM_XALO  104448
#define SM_WLO   139264   // rel +0, att +17408
#define SM_WHI   174080   // rel +0, att +17408; reused as ABs after hoist
#define SM_ABS   174080   // 2 batches x 4096 floats = 32768 B
#define SM_WD    208896   // wdr[128]
#define SM_B0R   209408
#define SM_WDA   209920
#define SM_B0A   210432
#define SM_PSM   210944   // 32 floats
#define SM_ATP   211072   // 128 floats
#define SM_ATTP  211584   // 4 x 128 floats
#define SM_ZV    213632   // 128 floats
#define SM_B2R   214144   // 64 floats
#define SMEM2_BYTES 214400

__device__ __forceinline__ uint32_t smem_u32(const void* p) {
    uint32_t a;
    asm("{ .reg .u64 t; cvta.to.shared.u64 t, %1; cvt.u32.u64 %0, t; }" : "=r"(a) : "l"(p));
    return a;
}
__device__ __forceinline__ void split2(float x0, float x1, uint32_t& hi, uint32_t& lo) {
    uint32_t h;
    asm("cvt.rn.bf16x2.f32 %0, %1, %2;" : "=r"(h) : "f"(x1), "f"(x0));
    float h0 = __uint_as_float(h << 16);
    float h1 = __uint_as_float(h & 0xffff0000u);
    float l0 = x0 - h0, l1 = x1 - h1;
    uint32_t l;
    asm("cvt.rn.bf16x2.f32 %0, %1, %2;" : "=r"(l) : "f"(l1), "f"(l0));
    hi = h; lo = l;
}
__device__ __forceinline__ void ldsm4(uint32_t r[4], uint32_t addr) {
    asm volatile("ldmatrix.sync.aligned.m8n8.x4.shared.b16 {%0,%1,%2,%3}, [%4];"
        : "=r"(r[0]), "=r"(r[1]), "=r"(r[2]), "=r"(r[3]) : "r"(addr));
}
__device__ __forceinline__ void mma16816(float d[4], const uint32_t a[4],
                                         uint32_t b0, uint32_t b1) {
    asm volatile("mma.sync.aligned.m16n8k16.row.col.f32.bf16.bf16.f32 "
        "{%0,%1,%2,%3}, {%4,%5,%6,%7}, {%8,%9}, {%0,%1,%2,%3};"
        : "+f"(d[0]), "+f"(d[1]), "+f"(d[2]), "+f"(d[3])
        : "r"(a[0]), "r"(a[1]), "r"(a[2]), "r"(a[3]), "r"(b0), "r"(b1));
}

__global__ __launch_bounds__(512, 1)
void k2_kernel(const float* __restrict__ s,
               const float* __restrict__ W_rel0, const float* __restrict__ b_rel0,
               const float* __restrict__ W_rel1, const float* __restrict__ b_rel1,
               const float* __restrict__ W_rel2, const float* __restrict__ b_rel2,
               const float* __restrict__ W_att0, const float* __restrict__ b_att0,
               const float* __restrict__ W_att1, const float* __restrict__ b_att1,
               const float* __restrict__ W_att2, const float* __restrict__ b_att2,
               float* __restrict__ out)
{
    extern __shared__ char smc[];
    const int tid  = threadIdx.x;
    const int wid  = tid >> 5;
    const int lane = tid & 31;
    const uint32_t smb = smem_u32(smc);

    const int half = wid >> 3;          // 0 rel, 1 att
    const int wg = wid & 7;
    const int wm = wg & 1;              // batch within superstep (64 rows)
    const int wn = wg >> 1;             // n-tile of 16 cols (0..3)

    float* wdr_s = (float*)(smc + SM_WD);
    float* b0r_s = (float*)(smc + SM_B0R);
    float* wda_s = (float*)(smc + SM_WDA);
    float* b0a_s = (float*)(smc + SM_B0A);
    float* psm   = (float*)(smc + SM_PSM);
    float* atp   = (float*)(smc + SM_ATP);
    float* attp  = (float*)(smc + SM_ATTP);
    float* zv    = (float*)(smc + SM_ZV);
    float* b2r_s = (float*)(smc + SM_B2R);
    float* ABs   = (float*)(smc + SM_ABS);

    // ---- stage W tiles bf16 hi/lo: [n=64][k padded 136], rel & att ----
    for (int idx = tid; idx < 4096; idx += 512) {
        int n = idx >> 6;
        int kp = (idx & 63) * 2;
        uint32_t off = (uint32_t)(n * 272 + kp * 2);
        uint32_t h, l;
        split2(W_rel1[kp*64 + n], W_rel1[(kp+1)*64 + n], h, l);
        *(uint32_t*)(smc + SM_WHI + off) = h;
        *(uint32_t*)(smc + SM_WLO + off) = l;
        split2(W_att1[kp*64 + n], W_att1[(kp+1)*64 + n], h, l);
        *(uint32_t*)(smc + SM_WHI + 17408 + off) = h;
        *(uint32_t*)(smc + SM_WLO + 17408 + off) = l;
    }
    if (tid < 128) {
        wdr_s[tid] = W_rel0[128*128 + tid];
        b0r_s[tid] = b_rel0[tid];
        wda_s[tid] = W_att0[128*128 + tid];
        b0a_s[tid] = b_att0[tid];
    }
    if (tid < 64) b2r_s[tid] = b_rel2[tid];
    const float b2a = b_att2[0];

    // per-thread column constants (4 cols: c0,c0+1,c0+8,c0+9)
    const int c0 = wn*16 + (lane & 3)*2;
    float b1c[4], w2c[4];
    if (half) {
        b1c[0] = b_att1[c0];   b1c[1] = b_att1[c0+1];
        b1c[2] = b_att1[c0+8]; b1c[3] = b_att1[c0+9];
        w2c[0] = W_att2[c0];   w2c[1] = W_att2[c0+1];
        w2c[2] = W_att2[c0+8]; w2c[3] = W_att2[c0+9];
    } else {
        b1c[0] = b_rel1[c0];   b1c[1] = b_rel1[c0+1];
        b1c[2] = b_rel1[c0+8]; b1c[3] = b_rel1[c0+9];
        w2c[0] = w2c[1] = w2c[2] = w2c[3] = 0.f;
    }
    __syncthreads();

    // ---- hoist B-hi fragments (W constant across batches) ----
    const uint32_t boffB = (uint32_t)((wn*16 + (lane & 7) + ((lane >> 4) << 3)) * 272
                                      + (((lane >> 3) & 1) * 8) * 2);
    const uint32_t whi = smb + SM_WHI + half*17408;
    const uint32_t wlo = smb + SM_WLO + half*17408;
    uint32_t BH[8][4];
#pragma unroll
    for (int ks = 0; ks < 8; ks++) ldsm4(BH[ks], whi + boffB + ks*32);
    __syncthreads();   // W-hi region now free -> ABs

    // ---- prime ABs + psm for superstep 0 ----
    {
        const float4* src = (const float4*)(g_AB + (size_t)(blockIdx.x*8) * 4096);
#pragma unroll
        for (int q = 0; q < 4; q++) ((float4*)ABs)[tid + q*512] = src[tid + q*512];
        if (tid < 32)
            psm[tid] = s[((size_t)(blockIdx.x*8 + (tid>>4)) * 8 + ((tid>>1)&7)) * 64 + (tid & 1)];
    }
    __syncthreads();

    const uint32_t xhi = smb + (half ? SM_XAHI : SM_XRHI);
    const uint32_t xlo = smb + (half ? SM_XALO : SM_XRLO);
    const uint32_t aoffA = (uint32_t)((wm*64 + (lane & 15)) * 272 + (lane >> 4) * 16);
    const int k0 = (tid & 31) * 4;       // X-build k-quad (fixed per thread)

    for (int db = 0; db < 4; db++) {
        const int b0 = blockIdx.x * 8 + db * 2;

        // ---- X build: 8 iters, one row (p_s) per warp-iter ----
#pragma unroll
        for (int it = 0; it < 8; it++) {
            const int p_s = it*16 + (tid >> 5);
            const int bbi = p_s >> 6, p = p_s & 63, i = p >> 3, j = p & 7;
            const float dx = psm[bbi*16 + 2*i]     - psm[bbi*16 + 2*j];
            const float dy = psm[bbi*16 + 2*i + 1] - psm[bbi*16 + 2*j + 1];
            const float d = dx*dx + dy*dy;
            const float* base = ABs + bbi*4096;
            const uint32_t off = (uint32_t)(p_s * 272 + (tid & 31) * 8);

            float4 Ar = *(const float4*)(base + i*512 + k0);
            float4 Br = *(const float4*)(base + j*512 + 128 + k0);
            float4 wd = *(const float4*)(wdr_s + k0);
            float4 bv = *(const float4*)(b0r_s + k0);
            float x0 = eluf(Ar.x + Br.x + fmaf(d, wd.x, bv.x));
            float x1 = eluf(Ar.y + Br.y + fmaf(d, wd.y, bv.y));
            float x2 = eluf(Ar.z + Br.z + fmaf(d, wd.z, bv.z));
            float x3 = eluf(Ar.w + Br.w + fmaf(d, wd.w, bv.w));
            uint32_t h0, l0, h1, l1;
            split2(x0, x1, h0, l0);
            split2(x2, x3, h1, l1);
            *(uint2*)(smc + SM_XRHI + off) = make_uint2(h0, h1);
            *(uint2*)(smc + SM_XRLO + off) = make_uint2(l0, l1);

            Ar = *(const float4*)(base + i*512 + 256 + k0);
            Br = *(const float4*)(base + j*512 + 384 + k0);
            wd = *(const float4*)(wda_s + k0);
            bv = *(const float4*)(b0a_s + k0);
            x0 = eluf(Ar.x + Br.x + fmaf(d, wd.x, bv.x));
            x1 = eluf(Ar.y + Br.y + fmaf(d, wd.y, bv.y));
            x2 = eluf(Ar.z + Br.z + fmaf(d, wd.z, bv.z));
            x3 = eluf(Ar.w + Br.w + fmaf(d, wd.w, bv.w));
            split2(x0, x1, h0, l0);
            split2(x2, x3, h1, l1);
            *(uint2*)(smc + SM_XAHI + off) = make_uint2(h0, h1);
            *(uint2*)(smc + SM_XALO + off) = make_uint2(l0, l1);
        }
        __syncthreads();

        // ---- prefetch next superstep's ABs + psm into registers ----
        const int nb = (db + 1) & 3;
        const int b0n = blockIdx.x * 8 + nb * 2;
        float4 pf[4];
        {
            const float4* src = (const float4*)(g_AB + (size_t)b0n * 4096);
#pragma unroll
            for (int q = 0; q < 4; q++) pf[q] = src[tid + q*512];
        }
        float psm_pf = 0.f;
        if (tid < 32)
            psm_pf = s[((size_t)(b0n + (tid>>4)) * 8 + ((tid>>1)&7)) * 64 + (tid & 1)];

        // ---- GEMM: D[4 mt][2 nt][4], hi/lo 3-product ----
        float d[4][2][4];
#pragma unroll
        for (int mt = 0; mt < 4; mt++)
#pragma unroll
            for (int nt = 0; nt < 2; nt++)
#pragma unroll
                for (int q = 0; q < 4; q++) d[mt][nt][q] = 0.f;

#pragma unroll
        for (int ks = 0; ks < 8; ks++) {
            uint32_t bl[4];
            ldsm4(bl, wlo + boffB + ks*32);
#pragma unroll
            for (int mt = 0; mt < 4; mt++) {
                uint32_t ah[4], al[4];
                ldsm4(ah, xhi + aoffA + mt*4352 + ks*32);
                ldsm4(al, xlo + aoffA + mt*4352 + ks*32);
                mma16816(d[mt][0], ah, BH[ks][0], BH[ks][1]);
                mma16816(d[mt][1], ah, BH[ks][2], BH[ks][3]);
                mma16816(d[mt][0], al, BH[ks][0], BH[ks][1]);
                mma16816(d[mt][1], al, BH[ks][2], BH[ks][3]);
                mma16816(d[mt][0], ah, bl[0], bl[1]);
                mma16816(d[mt][1], ah, bl[2], bl[3]);
            }
        }

        // ---- E1: att partial dots; rel elu in regs ----
        if (half) {
#pragma unroll
            for (int mt = 0; mt < 4; mt++) {
#pragma unroll
                for (int h = 0; h < 2; h++) {
                    float v0 = eluf(d[mt][0][h*2]     + b1c[0]);
                    float v1 = eluf(d[mt][0][h*2 + 1] + b1c[1]);
                    float v2 = eluf(d[mt][1][h*2]     + b1c[2]);
                    float v3 = eluf(d[mt][1][h*2 + 1] + b1c[3]);
                    float part = v0*w2c[0] + v1*w2c[1] + v2*w2c[2] + v3*w2c[3];
                    part += __shfl_xor_sync(0xffffffffu, part, 1);
                    part += __shfl_xor_sync(0xffffffffu, part, 2);
                    if ((lane & 3) == 0)
                        attp[wn*128 + wm*64 + mt*16 + h*8 + (lane >> 2)] = part;
                }
            }
        } else {
#pragma unroll
            for (int mt = 0; mt < 4; mt++)
#pragma unroll
                for (int nt = 0; nt < 2; nt++)
#pragma unroll
                    for (int q = 0; q < 4; q++)
                        d[mt][nt][q] = eluf(d[mt][nt][q] + b1c[nt*2 + (q & 1)]);
        }
        __syncthreads();

        // ---- E2: finalize att (sigmoid, diag mask) ----
        if (tid < 128) {
            const int p = tid & 63, i = p >> 3, j = p & 7;
            float a = attp[tid] + attp[128 + tid] + attp[256 + tid] + attp[384 + tid] + b2a;
            atp[tid] = (i == j) ? 0.f : 1.f / (1.f + __expf(-a));
        }
        __syncthreads();

        // ---- E3: rel scale by att + column reduce -> zv ----
        if (!half) {
            float at[4][2];
#pragma unroll
            for (int mt = 0; mt < 4; mt++) {
                at[mt][0] = atp[wm*64 + mt*16 + (lane >> 2)];
                at[mt][1] = atp[wm*64 + mt*16 + 8 + (lane >> 2)];
            }
            float z0 = 0.f, z1 = 0.f, z2 = 0.f, z3 = 0.f;
#pragma unroll
            for (int mt = 0; mt < 4; mt++) {
                z0 += d[mt][0][0]*at[mt][0] + d[mt][0][2]*at[mt][1];
                z1 += d[mt][0][1]*at[mt][0] + d[mt][0][3]*at[mt][1];
                z2 += d[mt][1][0]*at[mt][0] + d[mt][1][2]*at[mt][1];
                z3 += d[mt][1][1]*at[mt][0] + d[mt][1][3]*at[mt][1];
            }
#pragma unroll
            for (int m = 4; m <= 16; m <<= 1) {
                z0 += __shfl_xor_sync(0xffffffffu, z0, m);
                z1 += __shfl_xor_sync(0xffffffffu, z1, m);
                z2 += __shfl_xor_sync(0xffffffffu, z2, m);
                z3 += __shfl_xor_sync(0xffffffffu, z3, m);
            }
            if (lane < 4) {
                zv[wm*64 + c0]     = z0;
                zv[wm*64 + c0 + 1] = z1;
                zv[wm*64 + c0 + 8] = z2;
                zv[wm*64 + c0 + 9] = z3;
            }
        }
        __syncthreads();

        // ---- E4/E5 + pipelined ABs store ----
#pragma unroll
        for (int q = 0; q < 4; q++) ((float4*)ABs)[tid + q*512] = pf[q];
        if (tid < 32) psm[tid] = psm_pf;

        if (tid < 128) {
            const int bb = tid >> 6, c = tid & 63;
            float a0 = 0.f;
#pragma unroll
            for (int p = 0; p < 64; p++) a0 += atp[bb*64 + p];
            float o = zv[tid] + a0 * b2r_s[c];
#pragma unroll
            for (int k = 0; k < 64; k++)
                o = fmaf(zv[bb*64 + k], W_rel2[k*64 + c], o);
#pragma unroll
            for (int i = 0; i < 8; i++)
                o += g_SD[(size_t)((b0 + bb)*8 + i) * 64 + c];
            out[(size_t)(b0 + bb) * 64 + c] = o;
        }
        __syncthreads();
    }
}

// ---------------------------------------------------------------------------
extern "C" void kernel_launch(void* const* d_in, const int* in_sizes, int n_in,
                              void* d_out, int out_size)
{
    const float* s       = (const float*)d_in[0];
    const float* W_enc   = (const float*)d_in[1];
    const float* b_enc   = (const float*)d_in[2];
    const float* W_self0 = (const float*)d_in[3];
    const float* b_self0 = (const float*)d_in[4];
    const float* W_self1 = (const float*)d_in[5];
    const float* b_self1 = (const float*)d_in[6];
    const float* W_rel0  = (const float*)d_in[7];
    const float* b_rel0  = (const float*)d_in[8];
    const float* W_rel1  = (const float*)d_in[9];
    const float* b_rel1  = (const float*)d_in[10];
    const float* W_rel2  = (const float*)d_in[11];
    const float* b_rel2  = (const float*)d_in[12];
    const float* W_att0  = (const float*)d_in[13];
    const float* b_att0  = (const float*)d_in[14];
    const float* W_att1  = (const float*)d_in[15];
    const float* b_att1  = (const float*)d_in[16];
    const float* W_att2  = (const float*)d_in[17];
    const float* b_att2  = (const float*)d_in[18];
    float* out = (float*)d_out;

    const int smem1 = 13120 * 4;
    cudaFuncSetAttribute(k1_kernel, cudaFuncAttributeMaxDynamicSharedMemorySize, smem1);
    cudaFuncSetAttribute(k2_kernel, cudaFuncAttributeMaxDynamicSharedMemorySize, SMEM2_BYTES);

    k1_kernel<<<ROWS/64, 256, smem1>>>(s, W_enc, b_enc, W_self0, b_self0,
                                       W_self1, b_self1, W_rel0, W_att0);
    k2_kernel<<<BATCH/8, 512, SMEM2_BYTES>>>(s, W_rel0, b_rel0, W_rel1, b_rel1,
                                             W_rel2, b_rel2, W_att0, b_att0,
                                             W_att1, b_att1, W_att2, b_att2, out);
}

// round 8
// speedup vs baseline: 2.7997x; 1.5055x over previous
#include <cuda_runtime.h>
#include <stdint.h>
#include <math.h>

#define BATCH 8192
#define ROWS  65536

// Scratch (static device globals; allocation-free per harness rules)
__device__ float g_AB[(size_t)ROWS * 512];  // per row: [A_rel(128)|B_rel(128)|A_att(128)|B_att(128)]
__device__ float g_SD[(size_t)ROWS * 64];   // self_dyn per (b,i)
// Prepacked k1 weights, bf16 hi/lo, swizzled smem-image layout.
// [0:4096) Wenc | [4096:8192) Wself0 | [8192:12288) Wself1 | [12288 + ch*4096) Wcat chunk ch
__device__ __align__(16) uint16_t g_WpkH[45056];
__device__ __align__(16) uint16_t g_WpkL[45056];

__device__ __forceinline__ float eluf(float x) {
    return x > 0.f ? x : (__expf(x) - 1.f);
}
__device__ __forceinline__ uint32_t smem_u32(const void* p) {
    uint32_t a;
    asm("{ .reg .u64 t; cvta.to.shared.u64 t, %1; cvt.u32.u64 %0, t; }" : "=r"(a) : "l"(p));
    return a;
}
// split x0,x1 (memory order: x0 first) into packed bf16 hi pair + lo pair
__device__ __forceinline__ void split2(float x0, float x1, uint32_t& hi, uint32_t& lo) {
    uint32_t h;
    asm("cvt.rn.bf16x2.f32 %0, %1, %2;" : "=r"(h) : "f"(x1), "f"(x0));
    float h0 = __uint_as_float(h << 16);
    float h1 = __uint_as_float(h & 0xffff0000u);
    float l0 = x0 - h0, l1 = x1 - h1;
    uint32_t l;
    asm("cvt.rn.bf16x2.f32 %0, %1, %2;" : "=r"(l) : "f"(l1), "f"(l0));
    hi = h; lo = l;
}
__device__ __forceinline__ void ldsm4(uint32_t r[4], uint32_t addr) {
    asm volatile("ldmatrix.sync.aligned.m8n8.x4.shared.b16 {%0,%1,%2,%3}, [%4];"
        : "=r"(r[0]), "=r"(r[1]), "=r"(r[2]), "=r"(r[3]) : "r"(addr));
}
__device__ __forceinline__ void mma16816(float d[4], const uint32_t a[4],
                                         uint32_t b0, uint32_t b1) {
    asm volatile("mma.sync.aligned.m16n8k16.row.col.f32.bf16.bf16.f32 "
        "{%0,%1,%2,%3}, {%4,%5,%6,%7}, {%8,%9}, {%0,%1,%2,%3};"
        : "+f"(d[0]), "+f"(d[1]), "+f"(d[2]), "+f"(d[3])
        : "r"(a[0]), "r"(a[1]), "r"(a[2]), "r"(a[3]), "r"(b0), "r"(b1));
}

// ---------------------------------------------------------------------------
// K0: prepack k1 weights into bf16 hi/lo swizzled smem images.
// ---------------------------------------------------------------------------
__device__ __forceinline__ float catw(const float* Wr, const float* Wa, int k, int g) {
    if (g < 128) return Wr[k*128 + g];
    if (g < 256) return Wr[(64+k)*128 + (g-128)];
    if (g < 384) return Wa[k*128 + (g-256)];
    return Wa[(64+k)*128 + (g-384)];
}

__global__ void k0_kernel(const float* __restrict__ W_enc,
                          const float* __restrict__ W_self0,
                          const float* __restrict__ W_self1,
                          const float* __restrict__ W_rel0,
                          const float* __restrict__ W_att0)
{
    int e = blockIdx.x * 256 + threadIdx.x;   // pair index (k0 even)
    if (e >= 22528) return;
    int tile = e >> 11;           // 2048 pairs per 64x64 tile
    int idx = e & 2047;
    int n = idx & 63, k0 = (idx >> 6) * 2;
    float v0, v1;
    if (tile == 0)      { v0 = W_enc[k0*64+n];   v1 = W_enc[(k0+1)*64+n]; }
    else if (tile == 1) { v0 = W_self0[k0*64+n]; v1 = W_self0[(k0+1)*64+n]; }
    else if (tile == 2) { v0 = W_self1[k0*64+n]; v1 = W_self1[(k0+1)*64+n]; }
    else {
        int g = (tile - 3) * 64 + n;
        v0 = catw(W_rel0, W_att0, k0, g);
        v1 = catw(W_rel0, W_att0, k0 + 1, g);
    }
    uint32_t hb, lb;
    split2(v0, v1, hb, lb);
    uint32_t off16 = (uint32_t)(tile*4096 + n*64 + (((k0>>3)*8) ^ ((n&7)*8)) + (k0&7));
    *(uint32_t*)((char*)g_WpkH + off16*2) = hb;
    *(uint32_t*)((char*)g_WpkL + off16*2) = lb;
}

// ---------------------------------------------------------------------------
// K1v2: mma.sync bf16 hi/lo pipeline: s_enc -> h -> self_dyn -> AB projection.
// 512 threads, M=128 rows per block. Swizzled (XOR) bf16 tiles, K=64.
// ---------------------------------------------------------------------------
#define K1_XHI 0
#define K1_XLO 16384
#define K1_EHI 32768
#define K1_ELO 49152
#define K1_WSH 65536      // Wenc +0 | Ws0 +8192 | Ws1 +16384
#define K1_WSL 90112
#define K1_WC  114688     // buf0 hi | +8192 buf0 lo | +16384 buf1 hi | +24576 buf1 lo
#define K1_S01 147456     // 128 x 2 floats
#define SMEM1_BYTES 148480

// K=64 swizzled-tile GEMM: D[2mt][2nt][4] += Ahi@Bhi + Alo@Bhi + Ahi@Blo
__device__ __forceinline__ void gemm_k64(uint32_t AH, uint32_t AL,
                                         uint32_t BH, uint32_t BL,
                                         int wm, int wn, int lane, float d[2][2][4])
{
    const int nloc = wn*16 + (lane & 7) + ((lane >> 4) << 3);
    const int nsw  = (lane & 7) * 16;
    const int bkc0 = (lane >> 3) & 1;
    const int rloc0 = wm*32 + (lane & 15);
    const int rsw  = (lane & 7) * 16;
    const int akc0 = lane >> 4;
#pragma unroll
    for (int ks = 0; ks < 4; ks++) {
        uint32_t bh[4], bl[4];
        {
            uint32_t boff = (uint32_t)(nloc*128 + (((ks*2 + bkc0)*16) ^ nsw));
            ldsm4(bh, BH + boff);
            ldsm4(bl, BL + boff);
        }
#pragma unroll
        for (int mt = 0; mt < 2; mt++) {
            uint32_t aoff = (uint32_t)((rloc0 + mt*16)*128 + (((ks*2 + akc0)*16) ^ rsw));
            uint32_t ah[4], al[4];
            ldsm4(ah, AH + aoff);
            ldsm4(al, AL + aoff);
            mma16816(d[mt][0], ah, bh[0], bh[1]);
            mma16816(d[mt][1], ah, bh[2], bh[3]);
            mma16816(d[mt][0], al, bh[0], bh[1]);
            mma16816(d[mt][1], al, bh[2], bh[3]);
            mma16816(d[mt][0], ah, bl[0], bl[1]);
            mma16816(d[mt][1], ah, bl[2], bl[3]);
        }
    }
}
#define K1_ZERO(d) { _Pragma("unroll") for (int _m=0;_m<2;_m++) _Pragma("unroll") for (int _n=0;_n<2;_n++) _Pragma("unroll") for (int _q=0;_q<4;_q++) (d)[_m][_n][_q]=0.f; }

__global__ __launch_bounds__(512, 1)
void k1_kernel(const float* __restrict__ s,
               const float* __restrict__ b_enc,
               const float* __restrict__ b_self0,
               const float* __restrict__ b_self1)
{
    extern __shared__ char smc[];
    const uint32_t smb = smem_u32(smc);
    const int tid = threadIdx.x, lane = tid & 31, wid = tid >> 5;
    const int wm = wid & 3, wn = wid >> 2;
    const int row0 = blockIdx.x * 128;
    float* s01 = (float*)(smc + K1_S01);

    // stage small weights (linear copy of prepacked images)
    {
        const uint4* srcH = (const uint4*)g_WpkH;
        const uint4* srcL = (const uint4*)g_WpkL;
#pragma unroll
        for (int q = 0; q < 3; q++) {
            ((uint4*)(smc + K1_WSH))[tid + q*512] = srcH[tid + q*512];
            ((uint4*)(smc + K1_WSL))[tid + q*512] = srcL[tid + q*512];
        }
    }
    // prefetch Wcat chunk 0 into regs
    uint4 pH = ((const uint4*)g_WpkH)[1536 + tid];
    uint4 pL = ((const uint4*)g_WpkL)[1536 + tid];

    // load s tile -> XHI/XLO (+ s01)
#pragma unroll
    for (int it = 0; it < 4; it++) {
        int idx = tid + it*512;
        int r = idx >> 4, kq = idx & 15, k0 = kq*4;
        float4 v = *(const float4*)(s + (size_t)(row0 + r)*64 + k0);
        if (kq == 0) { s01[r*2] = v.x; s01[r*2+1] = v.y; }
        uint32_t h0, l0, h1, l1;
        split2(v.x, v.y, h0, l0);
        split2(v.z, v.w, h1, l1);
        uint32_t off = (uint32_t)(r*128 + (((k0>>3)*16) ^ ((r&7)*16)) + (k0&7)*2);
        *(uint2*)(smc + K1_XHI + off) = make_uint2(h0, h1);
        *(uint2*)(smc + K1_XLO + off) = make_uint2(l0, l1);
    }

    // per-thread column biases
    const int c0b = wn*16 + (lane & 3)*2;
    float be[4], bs0[4], bs1[4];
    be[0]  = b_enc[c0b];    be[1]  = b_enc[c0b+1];
    be[2]  = b_enc[c0b+8];  be[3]  = b_enc[c0b+9];
    bs0[0] = b_self0[c0b];   bs0[1] = b_self0[c0b+1];
    bs0[2] = b_self0[c0b+8]; bs0[3] = b_self0[c0b+9];
    bs1[0] = b_self1[c0b];   bs1[1] = b_self1[c0b+1];
    bs1[2] = b_self1[c0b+8]; bs1[3] = b_self1[c0b+9];
    __syncthreads();

    float d[2][2][4];

    // ---- GEMM1: s_enc = concat(s[:2], s@Wenc + b) -> EHI/ELO ----
    K1_ZERO(d);
    gemm_k64(smb + K1_XHI, smb + K1_XLO, smb + K1_WSH, smb + K1_WSL, wm, wn, lane, d);
#pragma unroll
    for (int mt = 0; mt < 2; mt++)
#pragma unroll
    for (int nt = 0; nt < 2; nt++)
#pragma unroll
    for (int h = 0; h < 2; h++) {
        int r = wm*32 + mt*16 + (lane >> 2) + h*8;
        int c0 = wn*16 + nt*8 + (lane & 3)*2;
        float v0 = d[mt][nt][h*2]     + be[nt*2];
        float v1 = d[mt][nt][h*2 + 1] + be[nt*2 + 1];
        if (c0 == 0) { v0 = s01[r*2]; v1 = s01[r*2+1]; }
        uint32_t hb, lb;
        split2(v0, v1, hb, lb);
        uint32_t off = (uint32_t)(r*128 + (((c0>>3)*16) ^ ((r&7)*16)) + (c0&7)*2);
        *(uint32_t*)(smc + K1_EHI + off) = hb;
        *(uint32_t*)(smc + K1_ELO + off) = lb;
    }
    __syncthreads();

    // ---- GEMM2: h = elu(s_enc@Ws0 + b) ; keep fp32 frags; write XHI/XLO ----
    K1_ZERO(d);
    gemm_k64(smb + K1_EHI, smb + K1_ELO, smb + K1_WSH + 8192, smb + K1_WSL + 8192,
             wm, wn, lane, d);
    float hf[2][2][4];
#pragma unroll
    for (int mt = 0; mt < 2; mt++)
#pragma unroll
    for (int nt = 0; nt < 2; nt++)
#pragma unroll
    for (int h = 0; h < 2; h++) {
        int r = wm*32 + mt*16 + (lane >> 2) + h*8;
        int c0 = wn*16 + nt*8 + (lane & 3)*2;
        float v0 = eluf(d[mt][nt][h*2]     + bs0[nt*2]);
        float v1 = eluf(d[mt][nt][h*2 + 1] + bs0[nt*2 + 1]);
        hf[mt][nt][h*2] = v0; hf[mt][nt][h*2+1] = v1;
        uint32_t hb, lb;
        split2(v0, v1, hb, lb);
        uint32_t off = (uint32_t)(r*128 + (((c0>>3)*16) ^ ((r&7)*16)) + (c0&7)*2);
        *(uint32_t*)(smc + K1_XHI + off) = hb;
        *(uint32_t*)(smc + K1_XLO + off) = lb;
    }
    __syncthreads();

    // stage Wcat chunk 0 (prefetched) while doing GEMM3
    *(uint4*)(smc + K1_WC + tid*16) = pH;
    *(uint4*)(smc + K1_WC + 8192 + tid*16) = pL;

    // ---- GEMM3: self_dyn = h@Ws1 + b + h -> g_SD ----
    K1_ZERO(d);
    gemm_k64(smb + K1_XHI, smb + K1_XLO, smb + K1_WSH + 16384, smb + K1_WSL + 16384,
             wm, wn, lane, d);
#pragma unroll
    for (int mt = 0; mt < 2; mt++)
#pragma unroll
    for (int nt = 0; nt < 2; nt++)
#pragma unroll
    for (int h = 0; h < 2; h++) {
        int r = wm*32 + mt*16 + (lane >> 2) + h*8;
        int c0 = wn*16 + nt*8 + (lane & 3)*2;
        float2 o;
        o.x = d[mt][nt][h*2]     + bs1[nt*2]     + hf[mt][nt][h*2];
        o.y = d[mt][nt][h*2 + 1] + bs1[nt*2 + 1] + hf[mt][nt][h*2 + 1];
        *(float2*)&g_SD[(size_t)(row0 + r)*64 + c0] = o;
    }
    __syncthreads();   // WC buf0 ready, XHI free

    // ---- GEMM4: AB = s_enc @ Wcat, 8 chunks, double-buffered streaming ----
    for (int ch = 0; ch < 8; ch++) {
        if (ch < 7) {
            pH = ((const uint4*)g_WpkH)[1536 + (ch+1)*512 + tid];
            pL = ((const uint4*)g_WpkL)[1536 + (ch+1)*512 + tid];
        }
        K1_ZERO(d);
        const uint32_t wcb = smb + K1_WC + (uint32_t)(ch & 1)*16384;
        gemm_k64(smb + K1_EHI, smb + K1_ELO, wcb, wcb + 8192, wm, wn, lane, d);
#pragma unroll
        for (int mt = 0; mt < 2; mt++)
#pragma unroll
        for (int nt = 0; nt < 2; nt++)
#pragma unroll
        for (int h = 0; h < 2; h++) {
            int r = wm*32 + mt*16 + (lane >> 2) + h*8;
            int c0 = wn*16 + nt*8 + (lane & 3)*2;
            float2 o;
            o.x = d[mt][nt][h*2];
            o.y = d[mt][nt][h*2 + 1];
            *(float2*)&g_AB[(size_t)(row0 + r)*512 + ch*64 + c0] = o;
        }
        if (ch < 7) {
            const uint32_t dstoff = K1_WC + (uint32_t)((ch+1) & 1)*16384;
            *(uint4*)(smc + dstoff + tid*16) = pH;
            *(uint4*)(smc + dstoff + 8192 + tid*16) = pL;
            __syncthreads();
        }
    }
}

// ===========================================================================
// K2: unchanged from R6 (passed at 351us).
// ===========================================================================
#define SM_XRHI  0
#define SM_XRLO  34816
#define SM_XAHI  69632
#define SM_XALO  104448
#define SM_WLO   139264   // rel +0, att +17408
#define SM_WHI   174080   // rel +0, att +17408; reused as ABs after hoist
#define SM_ABS   174080   // 2 batches x 4096 floats = 32768 B
#define SM_WD    208896   // wdr[128]
#define SM_B0R   209408
#define SM_WDA   209920
#define SM_B0A   210432
#define SM_PSM   210944   // 32 floats
#define SM_ATP   211072   // 128 floats
#define SM_ATTP  211584   // 4 x 128 floats
#define SM_ZV    213632   // 128 floats
#define SM_B2R   214144   // 64 floats
#define SMEM2_BYTES 214400

__global__ __launch_bounds__(512, 1)
void k2_kernel(const float* __restrict__ s,
               const float* __restrict__ W_rel0, const float* __restrict__ b_rel0,
               const float* __restrict__ W_rel1, const float* __restrict__ b_rel1,
               const float* __restrict__ W_rel2, const float* __restrict__ b_rel2,
               const float* __restrict__ W_att0, const float* __restrict__ b_att0,
               const float* __restrict__ W_att1, const float* __restrict__ b_att1,
               const float* __restrict__ W_att2, const float* __restrict__ b_att2,
               float* __restrict__ out)
{
    extern __shared__ char smc[];
    const int tid  = threadIdx.x;
    const int wid  = tid >> 5;
    const int lane = tid & 31;
    const uint32_t smb = smem_u32(smc);

    const int half = wid >> 3;          // 0 rel, 1 att
    const int wg = wid & 7;
    const int wm = wg & 1;              // batch within superstep (64 rows)
    const int wn = wg >> 1;             // n-tile of 16 cols (0..3)

    float* wdr_s = (float*)(smc + SM_WD);
    float* b0r_s = (float*)(smc + SM_B0R);
    float* wda_s = (float*)(smc + SM_WDA);
    float* b0a_s = (float*)(smc + SM_B0A);
    float* psm   = (float*)(smc + SM_PSM);
    float* atp   = (float*)(smc + SM_ATP);
    float* attp  = (float*)(smc + SM_ATTP);
    float* zv    = (float*)(smc + SM_ZV);
    float* b2r_s = (float*)(smc + SM_B2R);
    float* ABs   = (float*)(smc + SM_ABS);

    // ---- stage W tiles bf16 hi/lo: [n=64][k padded 136], rel & att ----
    for (int idx = tid; idx < 4096; idx += 512) {
        int n = idx >> 6;
        int kp = (idx & 63) * 2;
        uint32_t off = (uint32_t)(n * 272 + kp * 2);
        uint32_t h, l;
        split2(W_rel1[kp*64 + n], W_rel1[(kp+1)*64 + n], h, l);
        *(uint32_t*)(smc + SM_WHI + off) = h;
        *(uint32_t*)(smc + SM_WLO + off) = l;
        split2(W_att1[kp*64 + n], W_att1[(kp+1)*64 + n], h, l);
        *(uint32_t*)(smc + SM_WHI + 17408 + off) = h;
        *(uint32_t*)(smc + SM_WLO + 17408 + off) = l;
    }
    if (tid < 128) {
        wdr_s[tid] = W_rel0[128*128 + tid];
        b0r_s[tid] = b_rel0[tid];
        wda_s[tid] = W_att0[128*128 + tid];
        b0a_s[tid] = b_att0[tid];
    }
    if (tid < 64) b2r_s[tid] = b_rel2[tid];
    const float b2a = b_att2[0];

    // per-thread column constants (4 cols: c0,c0+1,c0+8,c0+9)
    const int c0 = wn*16 + (lane & 3)*2;
    float b1c[4], w2c[4];
    if (half) {
        b1c[0] = b_att1[c0];   b1c[1] = b_att1[c0+1];
        b1c[2] = b_att1[c0+8]; b1c[3] = b_att1[c0+9];
        w2c[0] = W_att2[c0];   w2c[1] = W_att2[c0+1];
        w2c[2] = W_att2[c0+8]; w2c[3] = W_att2[c0+9];
    } else {
        b1c[0] = b_rel1[c0];   b1c[1] = b_rel1[c0+1];
        b1c[2] = b_rel1[c0+8]; b1c[3] = b_rel1[c0+9];
        w2c[0] = w2c[1] = w2c[2] = w2c[3] = 0.f;
    }
    __syncthreads();

    // ---- hoist B-hi fragments (W constant across batches) ----
    const uint32_t boffB = (uint32_t)((wn*16 + (lane & 7) + ((lane >> 4) << 3)) * 272
                                      + (((lane >> 3) & 1) * 8) * 2);
    const uint32_t whi = smb + SM_WHI + half*17408;
    const uint32_t wlo = smb + SM_WLO + half*17408;
    uint32_t BH[8][4];
#pragma unroll
    for (int ks = 0; ks < 8; ks++) ldsm4(BH[ks], whi + boffB + ks*32);
    __syncthreads();   // W-hi region now free -> ABs

    // ---- prime ABs + psm for superstep 0 ----
    {
        const float4* src = (const float4*)(g_AB + (size_t)(blockIdx.x*8) * 4096);
#pragma unroll
        for (int q = 0; q < 4; q++) ((float4*)ABs)[tid + q*512] = src[tid + q*512];
        if (tid < 32)
            psm[tid] = s[((size_t)(blockIdx.x*8 + (tid>>4)) * 8 + ((tid>>1)&7)) * 64 + (tid & 1)];
    }
    __syncthreads();

    const uint32_t xhi = smb + (half ? SM_XAHI : SM_XRHI);
    const uint32_t xlo = smb + (half ? SM_XALO : SM_XRLO);
    const uint32_t aoffA = (uint32_t)((wm*64 + (lane & 15)) * 272 + (lane >> 4) * 16);
    const int k0 = (tid & 31) * 4;       // X-build k-quad (fixed per thread)

    for (int db = 0; db < 4; db++) {
        const int b0 = blockIdx.x * 8 + db * 2;

        // ---- X build: 8 iters, one row (p_s) per warp-iter ----
#pragma unroll
        for (int it = 0; it < 8; it++) {
            const int p_s = it*16 + (tid >> 5);
            const int bbi = p_s >> 6, p = p_s & 63, i = p >> 3, j = p & 7;
            const float dx = psm[bbi*16 + 2*i]     - psm[bbi*16 + 2*j];
            const float dy = psm[bbi*16 + 2*i + 1] - psm[bbi*16 + 2*j + 1];
            const float d = dx*dx + dy*dy;
            const float* base = ABs + bbi*4096;
            const uint32_t off = (uint32_t)(p_s * 272 + (tid & 31) * 8);

            float4 Ar = *(const float4*)(base + i*512 + k0);
            float4 Br = *(const float4*)(base + j*512 + 128 + k0);
            float4 wd = *(const float4*)(wdr_s + k0);
            float4 bv = *(const float4*)(b0r_s + k0);
            float x0 = eluf(Ar.x + Br.x + fmaf(d, wd.x, bv.x));
            float x1 = eluf(Ar.y + Br.y + fmaf(d, wd.y, bv.y));
            float x2 = eluf(Ar.z + Br.z + fmaf(d, wd.z, bv.z));
            float x3 = eluf(Ar.w + Br.w + fmaf(d, wd.w, bv.w));
            uint32_t h0, l0, h1, l1;
            split2(x0, x1, h0, l0);
            split2(x2, x3, h1, l1);
            *(uint2*)(smc + SM_XRHI + off) = make_uint2(h0, h1);
            *(uint2*)(smc + SM_XRLO + off) = make_uint2(l0, l1);

            Ar = *(const float4*)(base + i*512 + 256 + k0);
            Br = *(const float4*)(base + j*512 + 384 + k0);
            wd = *(const float4*)(wda_s + k0);
            bv = *(const float4*)(b0a_s + k0);
            x0 = eluf(Ar.x + Br.x + fmaf(d, wd.x, bv.x));
            x1 = eluf(Ar.y + Br.y + fmaf(d, wd.y, bv.y));
            x2 = eluf(Ar.z + Br.z + fmaf(d, wd.z, bv.z));
            x3 = eluf(Ar.w + Br.w + fmaf(d, wd.w, bv.w));
            split2(x0, x1, h0, l0);
            split2(x2, x3, h1, l1);
            *(uint2*)(smc + SM_XAHI + off) = make_uint2(h0, h1);
            *(uint2*)(smc + SM_XALO + off) = make_uint2(l0, l1);
        }
        __syncthreads();

        // ---- prefetch next superstep's ABs + psm into registers ----
        const int nb = (db + 1) & 3;
        const int b0n = blockIdx.x * 8 + nb * 2;
        float4 pf[4];
        {
            const float4* src = (const float4*)(g_AB + (size_t)b0n * 4096);
#pragma unroll
            for (int q = 0; q < 4; q++) pf[q] = src[tid + q*512];
        }
        float psm_pf = 0.f;
        if (tid < 32)
            psm_pf = s[((size_t)(b0n + (tid>>4)) * 8 + ((tid>>1)&7)) * 64 + (tid & 1)];

        // ---- GEMM: D[4 mt][2 nt][4], hi/lo 3-product ----
        float d[4][2][4];
#pragma unroll
        for (int mt = 0; mt < 4; mt++)
#pragma unroll
            for (int nt = 0; nt < 2; nt++)
#pragma unroll
                for (int q = 0; q < 4; q++) d[mt][nt][q] = 0.f;

#pragma unroll
        for (int ks = 0; ks < 8; ks++) {
            uint32_t bl[4];
            ldsm4(bl, wlo + boffB + ks*32);
#pragma unroll
            for (int mt = 0; mt < 4; mt++) {
                uint32_t ah[4], al[4];
                ldsm4(ah, xhi + aoffA + mt*4352 + ks*32);
                ldsm4(al, xlo + aoffA + mt*4352 + ks*32);
                mma16816(d[mt][0], ah, BH[ks][0], BH[ks][1]);
                mma16816(d[mt][1], ah, BH[ks][2], BH[ks][3]);
                mma16816(d[mt][0], al, BH[ks][0], BH[ks][1]);
                mma16816(d[mt][1], al, BH[ks][2], BH[ks][3]);
                mma16816(d[mt][0], ah, bl[0], bl[1]);
                mma16816(d[mt][1], ah, bl[2], bl[3]);
            }
        }

        // ---- E1: att partial dots; rel elu in regs ----
        if (half) {
#pragma unroll
            for (int mt = 0; mt < 4; mt++) {
#pragma unroll
                for (int h = 0; h < 2; h++) {
                    float v0 = eluf(d[mt][0][h*2]     + b1c[0]);
                    float v1 = eluf(d[mt][0][h*2 + 1] + b1c[1]);
                    float v2 = eluf(d[mt][1][h*2]     + b1c[2]);
                    float v3 = eluf(d[mt][1][h*2 + 1] + b1c[3]);
                    float part = v0*w2c[0] + v1*w2c[1] + v2*w2c[2] + v3*w2c[3];
                    part += __shfl_xor_sync(0xffffffffu, part, 1);
                    part += __shfl_xor_sync(0xffffffffu, part, 2);
                    if ((lane & 3) == 0)
                        attp[wn*128 + wm*64 + mt*16 + h*8 + (lane >> 2)] = part;
                }
            }
        } else {
#pragma unroll
            for (int mt = 0; mt < 4; mt++)
#pragma unroll
                for (int nt = 0; nt < 2; nt++)
#pragma unroll
                    for (int q = 0; q < 4; q++)
                        d[mt][nt][q] = eluf(d[mt][nt][q] + b1c[nt*2 + (q & 1)]);
        }
        __syncthreads();

        // ---- E2: finalize att (sigmoid, diag mask) ----
        if (tid < 128) {
            const int p = tid & 63, i = p >> 3, j = p & 7;
            float a = attp[tid] + attp[128 + tid] + attp[256 + tid] + attp[384 + tid] + b2a;
            atp[tid] = (i == j) ? 0.f : 1.f / (1.f + __expf(-a));
        }
        __syncthreads();

        // ---- E3: rel scale by att + column reduce -> zv ----
        if (!half) {
            float at[4][2];
#pragma unroll
            for (int mt = 0; mt < 4; mt++) {
                at[mt][0] = atp[wm*64 + mt*16 + (lane >> 2)];
                at[mt][1] = atp[wm*64 + mt*16 + 8 + (lane >> 2)];
            }
            float z0 = 0.f, z1 = 0.f, z2 = 0.f, z3 = 0.f;
#pragma unroll
            for (int mt = 0; mt < 4; mt++) {
                z0 += d[mt][0][0]*at[mt][0] + d[mt][0][2]*at[mt][1];
                z1 += d[mt][0][1]*at[mt][0] + d[mt][0][3]*at[mt][1];
                z2 += d[mt][1][0]*at[mt][0] + d[mt][1][2]*at[mt][1];
                z3 += d[mt][1][1]*at[mt][0] + d[mt][1][3]*at[mt][1];
            }
#pragma unroll
            for (int m = 4; m <= 16; m <<= 1) {
                z0 += __shfl_xor_sync(0xffffffffu, z0, m);
                z1 += __shfl_xor_sync(0xffffffffu, z1, m);
                z2 += __shfl_xor_sync(0xffffffffu, z2, m);
                z3 += __shfl_xor_sync(0xffffffffu, z3, m);
            }
            if (lane < 4) {
                zv[wm*64 + c0]     = z0;
                zv[wm*64 + c0 + 1] = z1;
                zv[wm*64 + c0 + 8] = z2;
                zv[wm*64 + c0 + 9] = z3;
            }
        }
        __syncthreads();

        // ---- E4/E5 + pipelined ABs store ----
#pragma unroll
        for (int q = 0; q < 4; q++) ((float4*)ABs)[tid + q*512] = pf[q];
        if (tid < 32) psm[tid] = psm_pf;

        if (tid < 128) {
            const int bb = tid >> 6, c = tid & 63;
            float a0 = 0.f;
#pragma unroll
            for (int p = 0; p < 64; p++) a0 += atp[bb*64 + p];
            float o = zv[tid] + a0 * b2r_s[c];
#pragma unroll
            for (int k = 0; k < 64; k++)
                o = fmaf(zv[bb*64 + k], W_rel2[k*64 + c], o);
#pragma unroll
            for (int i = 0; i < 8; i++)
                o += g_SD[(size_t)((b0 + bb)*8 + i) * 64 + c];
            out[(size_t)(b0 + bb) * 64 + c] = o;
        }
        __syncthreads();
    }
}

// ---------------------------------------------------------------------------
extern "C" void kernel_launch(void* const* d_in, const int* in_sizes, int n_in,
                              void* d_out, int out_size)
{
    const float* s       = (const float*)d_in[0];
    const float* W_enc   = (const float*)d_in[1];
    const float* b_enc   = (const float*)d_in[2];
    const float* W_self0 = (const float*)d_in[3];
    const float* b_self0 = (const float*)d_in[4];
    const float* W_self1 = (const float*)d_in[5];
    const float* b_self1 = (const float*)d_in[6];
    const float* W_rel0  = (const float*)d_in[7];
    const float* b_rel0  = (const float*)d_in[8];
    const float* W_rel1  = (const float*)d_in[9];
    const float* b_rel1  = (const float*)d_in[10];
    const float* W_rel2  = (const float*)d_in[11];
    const float* b_rel2  = (const float*)d_in[12];
    const float* W_att0  = (const float*)d_in[13];
    const float* b_att0  = (const float*)d_in[14];
    const float* W_att1  = (const float*)d_in[15];
    const float* b_att1  = (const float*)d_in[16];
    const float* W_att2  = (const float*)d_in[17];
    const float* b_att2  = (const float*)d_in[18];
    float* out = (float*)d_out;

    cudaFuncSetAttribute(k1_kernel, cudaFuncAttributeMaxDynamicSharedMemorySize, SMEM1_BYTES);
    cudaFuncSetAttribute(k2_kernel, cudaFuncAttributeMaxDynamicSharedMemorySize, SMEM2_BYTES);

    k0_kernel<<<88, 256>>>(W_enc, W_self0, W_self1, W_rel0, W_att0);
    k1_kernel<<<ROWS/128, 512, SMEM1_BYTES>>>(s, b_enc, b_self0, b_self1);
    k2_kernel<<<BATCH/8, 512, SMEM2_BYTES>>>(s, W_rel0, b_rel0, W_rel1, b_rel1,
                                             W_rel2, b_rel2, W_att0, b_att0,
                                             W_att1, b_att1, W_att2, b_att2, out);
}

// round 9
// speedup vs baseline: 3.1979x; 1.1423x over previous
#include <cuda_runtime.h>
#include <stdint.h>
#include <math.h>

#define BATCH 8192
#define ROWS  65536

// Scratch (static device globals; allocation-free per harness rules)
__device__ float g_AB[(size_t)ROWS * 512];  // per row: [A_rel(128)|B_rel(128)|A_att(128)|B_att(128)]
__device__ float g_SD[(size_t)ROWS * 64];   // self_dyn per (b,i)
// Prepacked k1 weights, bf16 hi/lo, swizzled smem-image layout.
__device__ __align__(16) uint16_t g_WpkH[45056];
__device__ __align__(16) uint16_t g_WpkL[45056];

__device__ __forceinline__ float eluf(float x) {
    return x > 0.f ? x : (__expf(x) - 1.f);
}
__device__ __forceinline__ uint32_t smem_u32(const void* p) {
    uint32_t a;
    asm("{ .reg .u64 t; cvta.to.shared.u64 t, %1; cvt.u32.u64 %0, t; }" : "=r"(a) : "l"(p));
    return a;
}
// split x0,x1 (memory order: x0 first) into packed bf16 hi pair + lo pair
__device__ __forceinline__ void split2(float x0, float x1, uint32_t& hi, uint32_t& lo) {
    uint32_t h;
    asm("cvt.rn.bf16x2.f32 %0, %1, %2;" : "=r"(h) : "f"(x1), "f"(x0));
    float h0 = __uint_as_float(h << 16);
    float h1 = __uint_as_float(h & 0xffff0000u);
    float l0 = x0 - h0, l1 = x1 - h1;
    uint32_t l;
    asm("cvt.rn.bf16x2.f32 %0, %1, %2;" : "=r"(l) : "f"(l1), "f"(l0));
    hi = h; lo = l;
}
__device__ __forceinline__ uint32_t f2tf32(float x) {
    uint32_t r;
    asm("cvt.rna.tf32.f32 %0, %1;" : "=r"(r) : "f"(x));
    return r;
}
__device__ __forceinline__ void ldsm4(uint32_t r[4], uint32_t addr) {
    asm volatile("ldmatrix.sync.aligned.m8n8.x4.shared.b16 {%0,%1,%2,%3}, [%4];"
        : "=r"(r[0]), "=r"(r[1]), "=r"(r[2]), "=r"(r[3]) : "r"(addr));
}
__device__ __forceinline__ void mma16816(float d[4], const uint32_t a[4],
                                         uint32_t b0, uint32_t b1) {
    asm volatile("mma.sync.aligned.m16n8k16.row.col.f32.bf16.bf16.f32 "
        "{%0,%1,%2,%3}, {%4,%5,%6,%7}, {%8,%9}, {%0,%1,%2,%3};"
        : "+f"(d[0]), "+f"(d[1]), "+f"(d[2]), "+f"(d[3])
        : "r"(a[0]), "r"(a[1]), "r"(a[2]), "r"(a[3]), "r"(b0), "r"(b1));
}
__device__ __forceinline__ void mma_tf32(float d[4], const uint32_t a[4],
                                         uint32_t b0, uint32_t b1) {
    asm volatile("mma.sync.aligned.m16n8k8.row.col.f32.tf32.tf32.f32 "
        "{%0,%1,%2,%3}, {%4,%5,%6,%7}, {%8,%9}, {%0,%1,%2,%3};"
        : "+f"(d[0]), "+f"(d[1]), "+f"(d[2]), "+f"(d[3])
        : "r"(a[0]), "r"(a[1]), "r"(a[2]), "r"(a[3]), "r"(b0), "r"(b1));
}

// ---------------------------------------------------------------------------
// K0: prepack k1 weights into bf16 hi/lo swizzled smem images. (unchanged)
// ---------------------------------------------------------------------------
__device__ __forceinline__ float catw(const float* Wr, const float* Wa, int k, int g) {
    if (g < 128) return Wr[k*128 + g];
    if (g < 256) return Wr[(64+k)*128 + (g-128)];
    if (g < 384) return Wa[k*128 + (g-256)];
    return Wa[(64+k)*128 + (g-384)];
}

__global__ void k0_kernel(const float* __restrict__ W_enc,
                          const float* __restrict__ W_self0,
                          const float* __restrict__ W_self1,
                          const float* __restrict__ W_rel0,
                          const float* __restrict__ W_att0)
{
    int e = blockIdx.x * 256 + threadIdx.x;
    if (e >= 22528) return;
    int tile = e >> 11;
    int idx = e & 2047;
    int n = idx & 63, k0 = (idx >> 6) * 2;
    float v0, v1;
    if (tile == 0)      { v0 = W_enc[k0*64+n];   v1 = W_enc[(k0+1)*64+n]; }
    else if (tile == 1) { v0 = W_self0[k0*64+n]; v1 = W_self0[(k0+1)*64+n]; }
    else if (tile == 2) { v0 = W_self1[k0*64+n]; v1 = W_self1[(k0+1)*64+n]; }
    else {
        int g = (tile - 3) * 64 + n;
        v0 = catw(W_rel0, W_att0, k0, g);
        v1 = catw(W_rel0, W_att0, k0 + 1, g);
    }
    uint32_t hb, lb;
    split2(v0, v1, hb, lb);
    uint32_t off16 = (uint32_t)(tile*4096 + n*64 + (((k0>>3)*8) ^ ((n&7)*8)) + (k0&7));
    *(uint32_t*)((char*)g_WpkH + off16*2) = hb;
    *(uint32_t*)((char*)g_WpkL + off16*2) = lb;
}

// ---------------------------------------------------------------------------
// K1v2: unchanged from R7 (passed; ~75us).
// ---------------------------------------------------------------------------
#define K1_XHI 0
#define K1_XLO 16384
#define K1_EHI 32768
#define K1_ELO 49152
#define K1_WSH 65536
#define K1_WSL 90112
#define K1_WC  114688
#define K1_S01 147456
#define SMEM1_BYTES 148480

__device__ __forceinline__ void gemm_k64(uint32_t AH, uint32_t AL,
                                         uint32_t BH, uint32_t BL,
                                         int wm, int wn, int lane, float d[2][2][4])
{
    const int nloc = wn*16 + (lane & 7) + ((lane >> 4) << 3);
    const int nsw  = (lane & 7) * 16;
    const int bkc0 = (lane >> 3) & 1;
    const int rloc0 = wm*32 + (lane & 15);
    const int rsw  = (lane & 7) * 16;
    const int akc0 = lane >> 4;
#pragma unroll
    for (int ks = 0; ks < 4; ks++) {
        uint32_t bh[4], bl[4];
        {
            uint32_t boff = (uint32_t)(nloc*128 + (((ks*2 + bkc0)*16) ^ nsw));
            ldsm4(bh, BH + boff);
            ldsm4(bl, BL + boff);
        }
#pragma unroll
        for (int mt = 0; mt < 2; mt++) {
            uint32_t aoff = (uint32_t)((rloc0 + mt*16)*128 + (((ks*2 + akc0)*16) ^ rsw));
            uint32_t ah[4], al[4];
            ldsm4(ah, AH + aoff);
            ldsm4(al, AL + aoff);
            mma16816(d[mt][0], ah, bh[0], bh[1]);
            mma16816(d[mt][1], ah, bh[2], bh[3]);
            mma16816(d[mt][0], al, bh[0], bh[1]);
            mma16816(d[mt][1], al, bh[2], bh[3]);
            mma16816(d[mt][0], ah, bl[0], bl[1]);
            mma16816(d[mt][1], ah, bl[2], bl[3]);
        }
    }
}
#define K1_ZERO(d) { _Pragma("unroll") for (int _m=0;_m<2;_m++) _Pragma("unroll") for (int _n=0;_n<2;_n++) _Pragma("unroll") for (int _q=0;_q<4;_q++) (d)[_m][_n][_q]=0.f; }

__global__ __launch_bounds__(512, 1)
void k1_kernel(const float* __restrict__ s,
               const float* __restrict__ b_enc,
               const float* __restrict__ b_self0,
               const float* __restrict__ b_self1)
{
    extern __shared__ char smc[];
    const uint32_t smb = smem_u32(smc);
    const int tid = threadIdx.x, lane = tid & 31, wid = tid >> 5;
    const int wm = wid & 3, wn = wid >> 2;
    const int row0 = blockIdx.x * 128;
    float* s01 = (float*)(smc + K1_S01);

    {
        const uint4* srcH = (const uint4*)g_WpkH;
        const uint4* srcL = (const uint4*)g_WpkL;
#pragma unroll
        for (int q = 0; q < 3; q++) {
            ((uint4*)(smc + K1_WSH))[tid + q*512] = srcH[tid + q*512];
            ((uint4*)(smc + K1_WSL))[tid + q*512] = srcL[tid + q*512];
        }
    }
    uint4 pH = ((const uint4*)g_WpkH)[1536 + tid];
    uint4 pL = ((const uint4*)g_WpkL)[1536 + tid];

#pragma unroll
    for (int it = 0; it < 4; it++) {
        int idx = tid + it*512;
        int r = idx >> 4, kq = idx & 15, k0 = kq*4;
        float4 v = *(const float4*)(s + (size_t)(row0 + r)*64 + k0);
        if (kq == 0) { s01[r*2] = v.x; s01[r*2+1] = v.y; }
        uint32_t h0, l0, h1, l1;
        split2(v.x, v.y, h0, l0);
        split2(v.z, v.w, h1, l1);
        uint32_t off = (uint32_t)(r*128 + (((k0>>3)*16) ^ ((r&7)*16)) + (k0&7)*2);
        *(uint2*)(smc + K1_XHI + off) = make_uint2(h0, h1);
        *(uint2*)(smc + K1_XLO + off) = make_uint2(l0, l1);
    }

    const int c0b = wn*16 + (lane & 3)*2;
    float be[4], bs0[4], bs1[4];
    be[0]  = b_enc[c0b];    be[1]  = b_enc[c0b+1];
    be[2]  = b_enc[c0b+8];  be[3]  = b_enc[c0b+9];
    bs0[0] = b_self0[c0b];   bs0[1] = b_self0[c0b+1];
    bs0[2] = b_self0[c0b+8]; bs0[3] = b_self0[c0b+9];
    bs1[0] = b_self1[c0b];   bs1[1] = b_self1[c0b+1];
    bs1[2] = b_self1[c0b+8]; bs1[3] = b_self1[c0b+9];
    __syncthreads();

    float d[2][2][4];

    K1_ZERO(d);
    gemm_k64(smb + K1_XHI, smb + K1_XLO, smb + K1_WSH, smb + K1_WSL, wm, wn, lane, d);
#pragma unroll
    for (int mt = 0; mt < 2; mt++)
#pragma unroll
    for (int nt = 0; nt < 2; nt++)
#pragma unroll
    for (int h = 0; h < 2; h++) {
        int r = wm*32 + mt*16 + (lane >> 2) + h*8;
        int c0 = wn*16 + nt*8 + (lane & 3)*2;
        float v0 = d[mt][nt][h*2]     + be[nt*2];
        float v1 = d[mt][nt][h*2 + 1] + be[nt*2 + 1];
        if (c0 == 0) { v0 = s01[r*2]; v1 = s01[r*2+1]; }
        uint32_t hb, lb;
        split2(v0, v1, hb, lb);
        uint32_t off = (uint32_t)(r*128 + (((c0>>3)*16) ^ ((r&7)*16)) + (c0&7)*2);
        *(uint32_t*)(smc + K1_EHI + off) = hb;
        *(uint32_t*)(smc + K1_ELO + off) = lb;
    }
    __syncthreads();

    K1_ZERO(d);
    gemm_k64(smb + K1_EHI, smb + K1_ELO, smb + K1_WSH + 8192, smb + K1_WSL + 8192,
             wm, wn, lane, d);
    float hf[2][2][4];
#pragma unroll
    for (int mt = 0; mt < 2; mt++)
#pragma unroll
    for (int nt = 0; nt < 2; nt++)
#pragma unroll
    for (int h = 0; h < 2; h++) {
        int r = wm*32 + mt*16 + (lane >> 2) + h*8;
        int c0 = wn*16 + nt*8 + (lane & 3)*2;
        float v0 = eluf(d[mt][nt][h*2]     + bs0[nt*2]);
        float v1 = eluf(d[mt][nt][h*2 + 1] + bs0[nt*2 + 1]);
        hf[mt][nt][h*2] = v0; hf[mt][nt][h*2+1] = v1;
        uint32_t hb, lb;
        split2(v0, v1, hb, lb);
        uint32_t off = (uint32_t)(r*128 + (((c0>>3)*16) ^ ((r&7)*16)) + (c0&7)*2);
        *(uint32_t*)(smc + K1_XHI + off) = hb;
        *(uint32_t*)(smc + K1_XLO + off) = lb;
    }
    __syncthreads();

    *(uint4*)(smc + K1_WC + tid*16) = pH;
    *(uint4*)(smc + K1_WC + 8192 + tid*16) = pL;

    K1_ZERO(d);
    gemm_k64(smb + K1_XHI, smb + K1_XLO, smb + K1_WSH + 16384, smb + K1_WSL + 16384,
             wm, wn, lane, d);
#pragma unroll
    for (int mt = 0; mt < 2; mt++)
#pragma unroll
    for (int nt = 0; nt < 2; nt++)
#pragma unroll
    for (int h = 0; h < 2; h++) {
        int r = wm*32 + mt*16 + (lane >> 2) + h*8;
        int c0 = wn*16 + nt*8 + (lane & 3)*2;
        float2 o;
        o.x = d[mt][nt][h*2]     + bs1[nt*2]     + hf[mt][nt][h*2];
        o.y = d[mt][nt][h*2 + 1] + bs1[nt*2 + 1] + hf[mt][nt][h*2 + 1];
        *(float2*)&g_SD[(size_t)(row0 + r)*64 + c0] = o;
    }
    __syncthreads();

    for (int ch = 0; ch < 8; ch++) {
        if (ch < 7) {
            pH = ((const uint4*)g_WpkH)[1536 + (ch+1)*512 + tid];
            pL = ((const uint4*)g_WpkL)[1536 + (ch+1)*512 + tid];
        }
        K1_ZERO(d);
        const uint32_t wcb = smb + K1_WC + (uint32_t)(ch & 1)*16384;
        gemm_k64(smb + K1_EHI, smb + K1_ELO, wcb, wcb + 8192, wm, wn, lane, d);
#pragma unroll
        for (int mt = 0; mt < 2; mt++)
#pragma unroll
        for (int nt = 0; nt < 2; nt++)
#pragma unroll
        for (int h = 0; h < 2; h++) {
            int r = wm*32 + mt*16 + (lane >> 2) + h*8;
            int c0 = wn*16 + nt*8 + (lane & 3)*2;
            float2 o;
            o.x = d[mt][nt][h*2];
            o.y = d[mt][nt][h*2 + 1];
            *(float2*)&g_AB[(size_t)(row0 + r)*512 + ch*64 + c0] = o;
        }
        if (ch < 7) {
            const uint32_t dstoff = K1_WC + (uint32_t)((ch+1) & 1)*16384;
            *(uint4*)(smc + dstoff + tid*16) = pH;
            *(uint4*)(smc + dstoff + 8192 + tid*16) = pL;
            __syncthreads();
        }
    }
}

// ===========================================================================
// K2v3: tf32 single-pass mma.sync. X tiles f32 XOR-swizzled; W f32 tiles.
// Supersteps of 2 batches (M=128), register epilogue, pipelined ABs.
// ===========================================================================
#define SM2_XR   0        // 128 x 512 B (f32, XOR swizzle); [0:512)=atp, [512:1024)=zv alias
#define SM2_XA   65536
#define SM2_WR   131072   // 64 x 512 B
#define SM2_WA   163840
#define SM2_ABS  196608   // 32768 B; first 2048 B alias attp
#define SM2_WD   229376   // wdr(512) b0r(512) wda(512) b0a(512) psm(128) b2r(256)
#define SMEM2_BYTES 231808

__global__ __launch_bounds__(512, 1)
void k2_kernel(const float* __restrict__ s,
               const float* __restrict__ W_rel0, const float* __restrict__ b_rel0,
               const float* __restrict__ W_rel1, const float* __restrict__ b_rel1,
               const float* __restrict__ W_rel2, const float* __restrict__ b_rel2,
               const float* __restrict__ W_att0, const float* __restrict__ b_att0,
               const float* __restrict__ W_att1, const float* __restrict__ b_att1,
               const float* __restrict__ W_att2, const float* __restrict__ b_att2,
               float* __restrict__ out)
{
    extern __shared__ char smc[];
    const int tid  = threadIdx.x;
    const int wid  = tid >> 5;
    const int lane = tid & 31;
    const uint32_t smb = smem_u32(smc);

    const int half = wid >> 3;          // 0 rel, 1 att
    const int wg = wid & 7;
    const int wm = wg & 1;              // batch within superstep (64 rows)
    const int wn = wg >> 1;             // n-tile of 16 cols (0..3)

    float* wdr_s = (float*)(smc + SM2_WD);
    float* b0r_s = (float*)(smc + SM2_WD + 512);
    float* wda_s = (float*)(smc + SM2_WD + 1024);
    float* b0a_s = (float*)(smc + SM2_WD + 1536);
    float* psm   = (float*)(smc + SM2_WD + 2048);
    float* b2r_s = (float*)(smc + SM2_WD + 2176);
    float* atp   = (float*)(smc + SM2_XR);          // alias: X dead when used
    float* zv    = (float*)(smc + SM2_XR + 512);    // alias
    float* attp  = (float*)(smc + SM2_ABS);         // alias: ABs consumed when used
    float* ABs   = (float*)(smc + SM2_ABS);

    // ---- stage W tiles (tf32, [n=64][k=128] f32, XOR swizzle) ----
    for (int idx = tid; idx < 8192; idx += 512) {
        int n = idx & 63, k = idx >> 6;
        uint32_t off = (uint32_t)(n*512 + ((k*4) ^ ((n&7)*16)));
        *(uint32_t*)(smc + SM2_WR + off) = f2tf32(W_rel1[k*64 + n]);
        *(uint32_t*)(smc + SM2_WA + off) = f2tf32(W_att1[k*64 + n]);
    }
    if (tid < 128) {
        wdr_s[tid] = W_rel0[128*128 + tid];
        b0r_s[tid] = b_rel0[tid];
        wda_s[tid] = W_att0[128*128 + tid];
        b0a_s[tid] = b_att0[tid];
    }
    if (tid < 64) b2r_s[tid] = b_rel2[tid];
    const float b2a = b_att2[0];

    // per-thread column constants (4 cols: c0,c0+1,c0+8,c0+9)
    const int c0 = wn*16 + (lane & 3)*2;
    float b1c[4], w2c[4];
    if (half) {
        b1c[0] = b_att1[c0];   b1c[1] = b_att1[c0+1];
        b1c[2] = b_att1[c0+8]; b1c[3] = b_att1[c0+9];
        w2c[0] = W_att2[c0];   w2c[1] = W_att2[c0+1];
        w2c[2] = W_att2[c0+8]; w2c[3] = W_att2[c0+9];
    } else {
        b1c[0] = b_rel1[c0];   b1c[1] = b_rel1[c0+1];
        b1c[2] = b_rel1[c0+8]; b1c[3] = b_rel1[c0+9];
        w2c[0] = w2c[1] = w2c[2] = w2c[3] = 0.f;
    }

    // ---- prime ABs + psm for superstep 0 ----
    {
        const float4* src = (const float4*)(g_AB + (size_t)(blockIdx.x*8) * 4096);
#pragma unroll
        for (int q = 0; q < 4; q++) ((float4*)ABs)[tid + q*512] = src[tid + q*512];
        if (tid < 32)
            psm[tid] = s[((size_t)(blockIdx.x*8 + (tid>>4)) * 8 + ((tid>>1)&7)) * 64 + (tid & 1)];
    }
    __syncthreads();

    // GEMM addressing constants
    const uint32_t xb = smb + (uint32_t)(half ? SM2_XA : SM2_XR);
    const uint32_t wb = smb + (uint32_t)(half ? SM2_WA : SM2_WR);
    // A (ldmatrix): lane -> matrix row
    const int r0l = wm*64 + ((lane >> 3) & 1)*8 + (lane & 7);
    const uint32_t abase = xb + (uint32_t)(r0l * 512);
    const uint32_t arsw  = (uint32_t)((r0l & 7) << 4);
    const uint32_t aklane = (uint32_t)(((lane >> 4) & 1) << 4);
    // B (scalar LDS): n = wn*16 + nt*8 + lane/4, k = ks*8 + lane%4 (+4)
    const uint32_t bn0 = wb + (uint32_t)((wn*16 + (lane >> 2)) * 512);
    const uint32_t bnsw = (uint32_t)((lane >> 2) << 4);
    const uint32_t bklo = (uint32_t)((lane & 3) << 2);
    // X-build store constants
    const uint32_t xsw  = (uint32_t)(((tid >> 5) & 7) << 4);
    const uint32_t xoff = ((uint32_t)((tid & 31) << 4)) ^ xsw;
    const int k0 = (tid & 31) * 4;       // X-build k-quad (fixed per thread)

    for (int db = 0; db < 4; db++) {
        const int b0 = blockIdx.x * 8 + db * 2;

        // ---- X build: 8 iters, one row (p_s) per warp-iter; store tf32 f32 ----
#pragma unroll
        for (int it = 0; it < 8; it++) {
            const int p_s = it*16 + wid;
            const int bbi = p_s >> 6, p = p_s & 63, i = p >> 3, j = p & 7;
            const float dx = psm[bbi*16 + 2*i]     - psm[bbi*16 + 2*j];
            const float dy = psm[bbi*16 + 2*i + 1] - psm[bbi*16 + 2*j + 1];
            const float d = dx*dx + dy*dy;
            const float* base = ABs + bbi*4096;
            const uint32_t roff = (uint32_t)(p_s * 512) + xoff;

            float4 Ar = *(const float4*)(base + i*512 + k0);
            float4 Br = *(const float4*)(base + j*512 + 128 + k0);
            float4 wd = *(const float4*)(wdr_s + k0);
            float4 bv = *(const float4*)(b0r_s + k0);
            uint4 o;
            o.x = f2tf32(eluf(Ar.x + Br.x + fmaf(d, wd.x, bv.x)));
            o.y = f2tf32(eluf(Ar.y + Br.y + fmaf(d, wd.y, bv.y)));
            o.z = f2tf32(eluf(Ar.z + Br.z + fmaf(d, wd.z, bv.z)));
            o.w = f2tf32(eluf(Ar.w + Br.w + fmaf(d, wd.w, bv.w)));
            *(uint4*)(smc + SM2_XR + roff) = o;

            Ar = *(const float4*)(base + i*512 + 256 + k0);
            Br = *(const float4*)(base + j*512 + 384 + k0);
            wd = *(const float4*)(wda_s + k0);
            bv = *(const float4*)(b0a_s + k0);
            o.x = f2tf32(eluf(Ar.x + Br.x + fmaf(d, wd.x, bv.x)));
            o.y = f2tf32(eluf(Ar.y + Br.y + fmaf(d, wd.y, bv.y)));
            o.z = f2tf32(eluf(Ar.z + Br.z + fmaf(d, wd.z, bv.z)));
            o.w = f2tf32(eluf(Ar.w + Br.w + fmaf(d, wd.w, bv.w)));
            *(uint4*)(smc + SM2_XA + roff) = o;
        }
        __syncthreads();

        // ---- prefetch next superstep's ABs + psm into registers ----
        const int nb = (db + 1) & 3;
        const int b0n = blockIdx.x * 8 + nb * 2;
        float4 pf[4];
        {
            const float4* src = (const float4*)(g_AB + (size_t)b0n * 4096);
#pragma unroll
            for (int q = 0; q < 4; q++) pf[q] = src[tid + q*512];
        }
        float psm_pf = 0.f;
        if (tid < 32)
            psm_pf = s[((size_t)(b0n + (tid>>4)) * 8 + ((tid>>1)&7)) * 64 + (tid & 1)];

        // ---- GEMM: tf32 single-pass, 16 k-steps ----
        float d[4][2][4];
#pragma unroll
        for (int mt = 0; mt < 4; mt++)
#pragma unroll
            for (int nt = 0; nt < 2; nt++)
#pragma unroll
                for (int q = 0; q < 4; q++) d[mt][nt][q] = 0.f;

#pragma unroll
        for (int ks = 0; ks < 16; ks++) {
            const uint32_t kb = (uint32_t)(ks * 32);
            uint32_t b00 = *(const uint32_t*)(smc + (bn0 - smb) + ((kb + bklo) ^ bnsw));
            uint32_t b01 = *(const uint32_t*)(smc + (bn0 - smb) + ((kb + bklo + 16) ^ bnsw));
            uint32_t b10 = *(const uint32_t*)(smc + (bn0 - smb) + 4096 + ((kb + bklo) ^ bnsw));
            uint32_t b11 = *(const uint32_t*)(smc + (bn0 - smb) + 4096 + ((kb + bklo + 16) ^ bnsw));
#pragma unroll
            for (int mt = 0; mt < 4; mt++) {
                uint32_t a[4];
                ldsm4(a, abase + (uint32_t)(mt * 8192) + ((kb + aklane) ^ arsw));
                mma_tf32(d[mt][0], a, b00, b01);
                mma_tf32(d[mt][1], a, b10, b11);
            }
        }

        // ---- E1: att partial dots; rel elu in regs ----
        if (half) {
#pragma unroll
            for (int mt = 0; mt < 4; mt++) {
#pragma unroll
                for (int h = 0; h < 2; h++) {
                    float v0 = eluf(d[mt][0][h*2]     + b1c[0]);
                    float v1 = eluf(d[mt][0][h*2 + 1] + b1c[1]);
                    float v2 = eluf(d[mt][1][h*2]     + b1c[2]);
                    float v3 = eluf(d[mt][1][h*2 + 1] + b1c[3]);
                    float part = v0*w2c[0] + v1*w2c[1] + v2*w2c[2] + v3*w2c[3];
                    part += __shfl_xor_sync(0xffffffffu, part, 1);
                    part += __shfl_xor_sync(0xffffffffu, part, 2);
                    if ((lane & 3) == 0)
                        attp[wn*128 + wm*64 + mt*16 + h*8 + (lane >> 2)] = part;
                }
            }
        } else {
#pragma unroll
            for (int mt = 0; mt < 4; mt++)
#pragma unroll
                for (int nt = 0; nt < 2; nt++)
#pragma unroll
                    for (int q = 0; q < 4; q++)
                        d[mt][nt][q] = eluf(d[mt][nt][q] + b1c[nt*2 + (q & 1)]);
        }
        __syncthreads();

        // ---- E2: finalize att (sigmoid, diag mask) ----
        if (tid < 128) {
            const int p = tid & 63, i = p >> 3, j = p & 7;
            float a = attp[tid] + attp[128 + tid] + attp[256 + tid] + attp[384 + tid] + b2a;
            atp[tid] = (i == j) ? 0.f : 1.f / (1.f + __expf(-a));
        }
        __syncthreads();

        // ---- E3: rel scale by att + column reduce -> zv ----
        if (!half) {
            float at[4][2];
#pragma unroll
            for (int mt = 0; mt < 4; mt++) {
                at[mt][0] = atp[wm*64 + mt*16 + (lane >> 2)];
                at[mt][1] = atp[wm*64 + mt*16 + 8 + (lane >> 2)];
            }
            float z0 = 0.f, z1 = 0.f, z2 = 0.f, z3 = 0.f;
#pragma unroll
            for (int mt = 0; mt < 4; mt++) {
                z0 += d[mt][0][0]*at[mt][0] + d[mt][0][2]*at[mt][1];
                z1 += d[mt][0][1]*at[mt][0] + d[mt][0][3]*at[mt][1];
                z2 += d[mt][1][0]*at[mt][0] + d[mt][1][2]*at[mt][1];
                z3 += d[mt][1][1]*at[mt][0] + d[mt][1][3]*at[mt][1];
            }
#pragma unroll
            for (int m = 4; m <= 16; m <<= 1) {
                z0 += __shfl_xor_sync(0xffffffffu, z0, m);
                z1 += __shfl_xor_sync(0xffffffffu, z1, m);
                z2 += __shfl_xor_sync(0xffffffffu, z2, m);
                z3 += __shfl_xor_sync(0xffffffffu, z3, m);
            }
            if (lane < 4) {
                zv[wm*64 + c0]     = z0;
                zv[wm*64 + c0 + 1] = z1;
                zv[wm*64 + c0 + 8] = z2;
                zv[wm*64 + c0 + 9] = z3;
            }
        }
        __syncthreads();

        // ---- E4/E5 + pipelined ABs store ----
#pragma unroll
        for (int q = 0; q < 4; q++) ((float4*)ABs)[tid + q*512] = pf[q];
        if (tid < 32) psm[tid] = psm_pf;

        if (tid < 128) {
            const int bb = tid >> 6, c = tid & 63;
            float a0 = 0.f;
#pragma unroll
            for (int p = 0; p < 64; p++) a0 += atp[bb*64 + p];
            float o = zv[tid] + a0 * b2r_s[c];
#pragma unroll
            for (int k = 0; k < 64; k++)
                o = fmaf(zv[bb*64 + k], W_rel2[k*64 + c], o);
#pragma unroll
            for (int i = 0; i < 8; i++)
                o += g_SD[(size_t)((b0 + bb)*8 + i) * 64 + c];
            out[(size_t)(b0 + bb) * 64 + c] = o;
        }
        __syncthreads();
    }
}

// ---------------------------------------------------------------------------
extern "C" void kernel_launch(void* const* d_in, const int* in_sizes, int n_in,
                              void* d_out, int out_size)
{
    const float* s       = (const float*)d_in[0];
    const float* W_enc   = (const float*)d_in[1];
    const float* b_enc   = (const float*)d_in[2];
    const float* W_self0 = (const float*)d_in[3];
    const float* b_self0 = (const float*)d_in[4];
    const float* W_self1 = (const float*)d_in[5];
    const float* b_self1 = (const float*)d_in[6];
    const float* W_rel0  = (const float*)d_in[7];
    const float* b_rel0  = (const float*)d_in[8];
    const float* W_rel1  = (const float*)d_in[9];
    const float* b_rel1  = (const float*)d_in[10];
    const float* W_rel2  = (const float*)d_in[11];
    const float* b_rel2  = (const float*)d_in[12];
    const float* W_att0  = (const float*)d_in[13];
    const float* b_att0  = (const float*)d_in[14];
    const float* W_att1  = (const float*)d_in[15];
    const float* b_att1  = (const float*)d_in[16];
    const float* W_att2  = (const float*)d_in[17];
    const float* b_att2  = (const float*)d_in[18];
    float* out = (float*)d_out;

    cudaFuncSetAttribute(k1_kernel, cudaFuncAttributeMaxDynamicSharedMemorySize, SMEM1_BYTES);
    cudaFuncSetAttribute(k2_kernel, cudaFuncAttributeMaxDynamicSharedMemorySize, SMEM2_BYTES);

    k0_kernel<<<88, 256>>>(W_enc, W_self0, W_self1, W_rel0, W_att0);
    k1_kernel<<<ROWS/128, 512, SMEM1_BYTES>>>(s, b_enc, b_self0, b_self1);
    k2_kernel<<<BATCH/8, 512, SMEM2_BYTES>>>(s, W_rel0, b_rel0, W_rel1, b_rel1,
                                             W_rel2, b_rel2, W_att0, b_att0,
                                             W_att1, b_att1, W_att2, b_att2, out);
}

// round 11
// speedup vs baseline: 3.2445x; 1.0146x over previous
#include <cuda_runtime.h>
#include <stdint.h>
#include <math.h>

#define BATCH 8192
#define ROWS  65536

// Scratch (static device globals; allocation-free per harness rules)
__device__ float g_AB[(size_t)ROWS * 512];  // per row: [A_rel(128)|B_rel(128)|A_att(128)|B_att(128)]
__device__ float g_SD[(size_t)ROWS * 64];   // self_dyn per (b,i)
// Prepacked k1 weights, bf16 hi/lo, swizzled smem-image layout.
__device__ __align__(16) uint16_t g_WpkH[45056];
__device__ __align__(16) uint16_t g_WpkL[45056];

__device__ __forceinline__ float eluf(float x) {
    return x > 0.f ? x : (__expf(x) - 1.f);
}
__device__ __forceinline__ uint32_t smem_u32(const void* p) {
    uint32_t a;
    asm("{ .reg .u64 t; cvta.to.shared.u64 t, %1; cvt.u32.u64 %0, t; }" : "=r"(a) : "l"(p));
    return a;
}
// split x0,x1 (memory order: x0 first) into packed bf16 hi pair + lo pair
__device__ __forceinline__ void split2(float x0, float x1, uint32_t& hi, uint32_t& lo) {
    uint32_t h;
    asm("cvt.rn.bf16x2.f32 %0, %1, %2;" : "=r"(h) : "f"(x1), "f"(x0));
    float h0 = __uint_as_float(h << 16);
    float h1 = __uint_as_float(h & 0xffff0000u);
    float l0 = x0 - h0, l1 = x1 - h1;
    uint32_t l;
    asm("cvt.rn.bf16x2.f32 %0, %1, %2;" : "=r"(l) : "f"(l1), "f"(l0));
    hi = h; lo = l;
}
__device__ __forceinline__ uint32_t f2tf32(float x) {
    uint32_t r;
    asm("cvt.rna.tf32.f32 %0, %1;" : "=r"(r) : "f"(x));
    return r;
}
__device__ __forceinline__ void ldsm4(uint32_t r[4], uint32_t addr) {
    asm volatile("ldmatrix.sync.aligned.m8n8.x4.shared.b16 {%0,%1,%2,%3}, [%4];"
        : "=r"(r[0]), "=r"(r[1]), "=r"(r[2]), "=r"(r[3]) : "r"(addr));
}
__device__ __forceinline__ void mma16816(float d[4], const uint32_t a[4],
                                         uint32_t b0, uint32_t b1) {
    asm volatile("mma.sync.aligned.m16n8k16.row.col.f32.bf16.bf16.f32 "
        "{%0,%1,%2,%3}, {%4,%5,%6,%7}, {%8,%9}, {%0,%1,%2,%3};"
        : "+f"(d[0]), "+f"(d[1]), "+f"(d[2]), "+f"(d[3])
        : "r"(a[0]), "r"(a[1]), "r"(a[2]), "r"(a[3]), "r"(b0), "r"(b1));
}
__device__ __forceinline__ void mma_tf32(float d[4], const uint32_t a[4],
                                         uint32_t b0, uint32_t b1) {
    asm volatile("mma.sync.aligned.m16n8k8.row.col.f32.tf32.tf32.f32 "
        "{%0,%1,%2,%3}, {%4,%5,%6,%7}, {%8,%9}, {%0,%1,%2,%3};"
        : "+f"(d[0]), "+f"(d[1]), "+f"(d[2]), "+f"(d[3])
        : "r"(a[0]), "r"(a[1]), "r"(a[2]), "r"(a[3]), "r"(b0), "r"(b1));
}

// ---------------------------------------------------------------------------
// K0: prepack k1 weights into bf16 hi/lo swizzled smem images. (unchanged)
// ---------------------------------------------------------------------------
__device__ __forceinline__ float catw(const float* Wr, const float* Wa, int k, int g) {
    if (g < 128) return Wr[k*128 + g];
    if (g < 256) return Wr[(64+k)*128 + (g-128)];
    if (g < 384) return Wa[k*128 + (g-256)];
    return Wa[(64+k)*128 + (g-384)];
}

__global__ void k0_kernel(const float* __restrict__ W_enc,
                          const float* __restrict__ W_self0,
                          const float* __restrict__ W_self1,
                          const float* __restrict__ W_rel0,
                          const float* __restrict__ W_att0)
{
    int e = blockIdx.x * 256 + threadIdx.x;
    if (e >= 22528) return;
    int tile = e >> 11;
    int idx = e & 2047;
    int n = idx & 63, k0 = (idx >> 6) * 2;
    float v0, v1;
    if (tile == 0)      { v0 = W_enc[k0*64+n];   v1 = W_enc[(k0+1)*64+n]; }
    else if (tile == 1) { v0 = W_self0[k0*64+n]; v1 = W_self0[(k0+1)*64+n]; }
    else if (tile == 2) { v0 = W_self1[k0*64+n]; v1 = W_self1[(k0+1)*64+n]; }
    else {
        int g = (tile - 3) * 64 + n;
        v0 = catw(W_rel0, W_att0, k0, g);
        v1 = catw(W_rel0, W_att0, k0 + 1, g);
    }
    uint32_t hb, lb;
    split2(v0, v1, hb, lb);
    uint32_t off16 = (uint32_t)(tile*4096 + n*64 + (((k0>>3)*8) ^ ((n&7)*8)) + (k0&7));
    *(uint32_t*)((char*)g_WpkH + off16*2) = hb;
    *(uint32_t*)((char*)g_WpkL + off16*2) = lb;
}

// ---------------------------------------------------------------------------
// K1v2: unchanged from R7/R8 (passed; ~75us).
// ---------------------------------------------------------------------------
#define K1_XHI 0
#define K1_XLO 16384
#define K1_EHI 32768
#define K1_ELO 49152
#define K1_WSH 65536
#define K1_WSL 90112
#define K1_WC  114688
#define K1_S01 147456
#define SMEM1_BYTES 148480

__device__ __forceinline__ void gemm_k64(uint32_t AH, uint32_t AL,
                                         uint32_t BH, uint32_t BL,
                                         int wm, int wn, int lane, float d[2][2][4])
{
    const int nloc = wn*16 + (lane & 7) + ((lane >> 4) << 3);
    const int nsw  = (lane & 7) * 16;
    const int bkc0 = (lane >> 3) & 1;
    const int rloc0 = wm*32 + (lane & 15);
    const int rsw  = (lane & 7) * 16;
    const int akc0 = lane >> 4;
#pragma unroll
    for (int ks = 0; ks < 4; ks++) {
        uint32_t bh[4], bl[4];
        {
            uint32_t boff = (uint32_t)(nloc*128 + (((ks*2 + bkc0)*16) ^ nsw));
            ldsm4(bh, BH + boff);
            ldsm4(bl, BL + boff);
        }
#pragma unroll
        for (int mt = 0; mt < 2; mt++) {
            uint32_t aoff = (uint32_t)((rloc0 + mt*16)*128 + (((ks*2 + akc0)*16) ^ rsw));
            uint32_t ah[4], al[4];
            ldsm4(ah, AH + aoff);
            ldsm4(al, AL + aoff);
            mma16816(d[mt][0], ah, bh[0], bh[1]);
            mma16816(d[mt][1], ah, bh[2], bh[3]);
            mma16816(d[mt][0], al, bh[0], bh[1]);
            mma16816(d[mt][1], al, bh[2], bh[3]);
            mma16816(d[mt][0], ah, bl[0], bl[1]);
            mma16816(d[mt][1], ah, bl[2], bl[3]);
        }
    }
}
#define K1_ZERO(d) { _Pragma("unroll") for (int _m=0;_m<2;_m++) _Pragma("unroll") for (int _n=0;_n<2;_n++) _Pragma("unroll") for (int _q=0;_q<4;_q++) (d)[_m][_n][_q]=0.f; }

__global__ __launch_bounds__(512, 1)
void k1_kernel(const float* __restrict__ s,
               const float* __restrict__ b_enc,
               const float* __restrict__ b_self0,
               const float* __restrict__ b_self1)
{
    extern __shared__ char smc[];
    const uint32_t smb = smem_u32(smc);
    const int tid = threadIdx.x, lane = tid & 31, wid = tid >> 5;
    const int wm = wid & 3, wn = wid >> 2;
    const int row0 = blockIdx.x * 128;
    float* s01 = (float*)(smc + K1_S01);

    {
        const uint4* srcH = (const uint4*)g_WpkH;
        const uint4* srcL = (const uint4*)g_WpkL;
#pragma unroll
        for (int q = 0; q < 3; q++) {
            ((uint4*)(smc + K1_WSH))[tid + q*512] = srcH[tid + q*512];
            ((uint4*)(smc + K1_WSL))[tid + q*512] = srcL[tid + q*512];
        }
    }
    uint4 pH = ((const uint4*)g_WpkH)[1536 + tid];
    uint4 pL = ((const uint4*)g_WpkL)[1536 + tid];

#pragma unroll
    for (int it = 0; it < 4; it++) {
        int idx = tid + it*512;
        int r = idx >> 4, kq = idx & 15, k0 = kq*4;
        float4 v = *(const float4*)(s + (size_t)(row0 + r)*64 + k0);
        if (kq == 0) { s01[r*2] = v.x; s01[r*2+1] = v.y; }
        uint32_t h0, l0, h1, l1;
        split2(v.x, v.y, h0, l0);
        split2(v.z, v.w, h1, l1);
        uint32_t off = (uint32_t)(r*128 + (((k0>>3)*16) ^ ((r&7)*16)) + (k0&7)*2);
        *(uint2*)(smc + K1_XHI + off) = make_uint2(h0, h1);
        *(uint2*)(smc + K1_XLO + off) = make_uint2(l0, l1);
    }

    const int c0b = wn*16 + (lane & 3)*2;
    float be[4], bs0[4], bs1[4];
    be[0]  = b_enc[c0b];    be[1]  = b_enc[c0b+1];
    be[2]  = b_enc[c0b+8];  be[3]  = b_enc[c0b+9];
    bs0[0] = b_self0[c0b];   bs0[1] = b_self0[c0b+1];
    bs0[2] = b_self0[c0b+8]; bs0[3] = b_self0[c0b+9];
    bs1[0] = b_self1[c0b];   bs1[1] = b_self1[c0b+1];
    bs1[2] = b_self1[c0b+8]; bs1[3] = b_self1[c0b+9];
    __syncthreads();

    float d[2][2][4];

    K1_ZERO(d);
    gemm_k64(smb + K1_XHI, smb + K1_XLO, smb + K1_WSH, smb + K1_WSL, wm, wn, lane, d);
#pragma unroll
    for (int mt = 0; mt < 2; mt++)
#pragma unroll
    for (int nt = 0; nt < 2; nt++)
#pragma unroll
    for (int h = 0; h < 2; h++) {
        int r = wm*32 + mt*16 + (lane >> 2) + h*8;
        int c0 = wn*16 + nt*8 + (lane & 3)*2;
        float v0 = d[mt][nt][h*2]     + be[nt*2];
        float v1 = d[mt][nt][h*2 + 1] + be[nt*2 + 1];
        if (c0 == 0) { v0 = s01[r*2]; v1 = s01[r*2+1]; }
        uint32_t hb, lb;
        split2(v0, v1, hb, lb);
        uint32_t off = (uint32_t)(r*128 + (((c0>>3)*16) ^ ((r&7)*16)) + (c0&7)*2);
        *(uint32_t*)(smc + K1_EHI + off) = hb;
        *(uint32_t*)(smc + K1_ELO + off) = lb;
    }
    __syncthreads();

    K1_ZERO(d);
    gemm_k64(smb + K1_EHI, smb + K1_ELO, smb + K1_WSH + 8192, smb + K1_WSL + 8192,
             wm, wn, lane, d);
    float hf[2][2][4];
#pragma unroll
    for (int mt = 0; mt < 2; mt++)
#pragma unroll
    for (int nt = 0; nt < 2; nt++)
#pragma unroll
    for (int h = 0; h < 2; h++) {
        int r = wm*32 + mt*16 + (lane >> 2) + h*8;
        int c0 = wn*16 + nt*8 + (lane & 3)*2;
        float v0 = eluf(d[mt][nt][h*2]     + bs0[nt*2]);
        float v1 = eluf(d[mt][nt][h*2 + 1] + bs0[nt*2 + 1]);
        hf[mt][nt][h*2] = v0; hf[mt][nt][h*2+1] = v1;
        uint32_t hb, lb;
        split2(v0, v1, hb, lb);
        uint32_t off = (uint32_t)(r*128 + (((c0>>3)*16) ^ ((r&7)*16)) + (c0&7)*2);
        *(uint32_t*)(smc + K1_XHI + off) = hb;
        *(uint32_t*)(smc + K1_XLO + off) = lb;
    }
    __syncthreads();

    *(uint4*)(smc + K1_WC + tid*16) = pH;
    *(uint4*)(smc + K1_WC + 8192 + tid*16) = pL;

    K1_ZERO(d);
    gemm_k64(smb + K1_XHI, smb + K1_XLO, smb + K1_WSH + 16384, smb + K1_WSL + 16384,
             wm, wn, lane, d);
#pragma unroll
    for (int mt = 0; mt < 2; mt++)
#pragma unroll
    for (int nt = 0; nt < 2; nt++)
#pragma unroll
    for (int h = 0; h < 2; h++) {
        int r = wm*32 + mt*16 + (lane >> 2) + h*8;
        int c0 = wn*16 + nt*8 + (lane & 3)*2;
        float2 o;
        o.x = d[mt][nt][h*2]     + bs1[nt*2]     + hf[mt][nt][h*2];
        o.y = d[mt][nt][h*2 + 1] + bs1[nt*2 + 1] + hf[mt][nt][h*2 + 1];
        *(float2*)&g_SD[(size_t)(row0 + r)*64 + c0] = o;
    }
    __syncthreads();

    for (int ch = 0; ch < 8; ch++) {
        if (ch < 7) {
            pH = ((const uint4*)g_WpkH)[1536 + (ch+1)*512 + tid];
            pL = ((const uint4*)g_WpkL)[1536 + (ch+1)*512 + tid];
        }
        K1_ZERO(d);
        const uint32_t wcb = smb + K1_WC + (uint32_t)(ch & 1)*16384;
        gemm_k64(smb + K1_EHI, smb + K1_ELO, wcb, wcb + 8192, wm, wn, lane, d);
#pragma unroll
        for (int mt = 0; mt < 2; mt++)
#pragma unroll
        for (int nt = 0; nt < 2; nt++)
#pragma unroll
        for (int h = 0; h < 2; h++) {
            int r = wm*32 + mt*16 + (lane >> 2) + h*8;
            int c0 = wn*16 + nt*8 + (lane & 3)*2;
            float2 o;
            o.x = d[mt][nt][h*2];
            o.y = d[mt][nt][h*2 + 1];
            *(float2*)&g_AB[(size_t)(row0 + r)*512 + ch*64 + c0] = o;
        }
        if (ch < 7) {
            const uint32_t dstoff = K1_WC + (uint32_t)((ch+1) & 1)*16384;
            *(uint4*)(smc + dstoff + tid*16) = pH;
            *(uint4*)(smc + dstoff + 8192 + tid*16) = pL;
            __syncthreads();
        }
    }
}

// ===========================================================================
// K2v4b: tf32 mma.sync, decoupled rel/att pipelines via named barriers.
// FIX vs R9: att-half barrier between E4 (atp reads) and the pf store that
// clobbers the atp alias region (row-2 att cols).
// ===========================================================================
#define SM2_XR   0        // 128 x 512 B (f32, XOR swizzle), rel X
#define SM2_XA   65536    // att X
#define SM2_WR   131072   // 64 x 512 B
#define SM2_WA   163840
#define SM2_ABS  196608   // 32768 B; rel cols (f 0-255/row) | att cols (256-511)
#define SM2_WD   229376   // psm[2][32] | b2r[64] | zv[128]
#define SMEM2_BYTES 230400

// aliases inside ABs att columns (floats):
//   attp(i), i<512:  ABsf[(i>>8)*512 + 256 + (i&255)]   (rows 0-1 att cols)
//   atp(i),  i<128:  ABsf[1280 + i]                      (row 2 att cols)

__global__ __launch_bounds__(512, 1)
void k2_kernel(const float* __restrict__ s,
               const float* __restrict__ W_rel0, const float* __restrict__ b_rel0,
               const float* __restrict__ W_rel1, const float* __restrict__ b_rel1,
               const float* __restrict__ W_rel2, const float* __restrict__ b_rel2,
               const float* __restrict__ W_att0, const float* __restrict__ b_att0,
               const float* __restrict__ W_att1, const float* __restrict__ b_att1,
               const float* __restrict__ W_att2, const float* __restrict__ b_att2,
               float* __restrict__ out)
{
    extern __shared__ char smc[];
    const int tid  = threadIdx.x;
    const int wid  = tid >> 5;
    const int lane = tid & 31;
    const uint32_t smb = smem_u32(smc);

    const int half = wid >> 3;          // 0 rel, 1 att
    const int wg = wid & 7;
    const int wm = wg & 1;              // batch within superstep (64 rows)
    const int wn = wg >> 1;             // n-tile of 16 cols (0..3)
    const int t2 = tid & 255;           // index within half

    float* psmbuf = (float*)(smc + SM2_WD);         // [2][32]
    float* b2r_s  = (float*)(smc + SM2_WD + 256);   // [64]
    float* zv     = (float*)(smc + SM2_WD + 512);   // [128]
    float* ABsf   = (float*)(smc + SM2_ABS);

    // ---- stage W tiles (tf32, [n=64][k=128] f32, XOR swizzle) ----
    for (int idx = tid; idx < 8192; idx += 512) {
        int n = idx & 63, k = idx >> 6;
        uint32_t off = (uint32_t)(n*512 + ((k*4) ^ ((n&7)*16)));
        *(uint32_t*)(smc + SM2_WR + off) = f2tf32(W_rel1[k*64 + n]);
        *(uint32_t*)(smc + SM2_WA + off) = f2tf32(W_att1[k*64 + n]);
    }
    if (tid < 64) b2r_s[tid] = b_rel2[tid];
    const float b2a = b_att2[0];

    // per-thread column constants
    const int c0 = wn*16 + (lane & 3)*2;
    float b1c[4], w2c[4];
    if (half) {
        b1c[0] = b_att1[c0];   b1c[1] = b_att1[c0+1];
        b1c[2] = b_att1[c0+8]; b1c[3] = b_att1[c0+9];
        w2c[0] = W_att2[c0];   w2c[1] = W_att2[c0+1];
        w2c[2] = W_att2[c0+8]; w2c[3] = W_att2[c0+9];
    } else {
        b1c[0] = b_rel1[c0];   b1c[1] = b_rel1[c0+1];
        b1c[2] = b_rel1[c0+8]; b1c[3] = b_rel1[c0+9];
        w2c[0] = w2c[1] = w2c[2] = w2c[3] = 0.f;
    }
    // X-build constants (k-quad = lane*4, own half)
    float4 wd4, bv4;
    if (half) {
        wd4 = *(const float4*)&W_att0[128*128 + lane*4];
        bv4 = *(const float4*)&b_att0[lane*4];
    } else {
        wd4 = *(const float4*)&W_rel0[128*128 + lane*4];
        bv4 = *(const float4*)&b_rel0[lane*4];
    }

    // ---- prime ABs + psm[0] ----
    {
        const float4* src = (const float4*)(g_AB + (size_t)(blockIdx.x*8) * 4096);
#pragma unroll
        for (int q = 0; q < 4; q++) ((float4*)ABsf)[tid + q*512] = src[tid + q*512];
        if (tid < 32)
            psmbuf[tid] = s[((size_t)(blockIdx.x*8 + (tid>>4)) * 8 + ((tid>>1)&7)) * 64 + (tid & 1)];
    }
    __syncthreads();

    // GEMM addressing constants (identical math to R8)
    const uint32_t xbo = (uint32_t)(half ? SM2_XA : SM2_XR);
    const int r0l = wm*64 + ((lane >> 3) & 1)*8 + (lane & 7);
    const uint32_t abase = smb + xbo + (uint32_t)(r0l * 512);
    const uint32_t arsw  = (uint32_t)((r0l & 7) << 4);
    const uint32_t aklane = (uint32_t)(((lane >> 4) & 1) << 4);
    const uint32_t wboff = (uint32_t)(half ? SM2_WA : SM2_WR)
                         + (uint32_t)((wn*16 + (lane >> 2)) * 512);
    const uint32_t bnsw = (uint32_t)((lane >> 2) << 4);
    const uint32_t bklo = (uint32_t)((lane & 3) << 2);
    const uint32_t xoff = ((uint32_t)(lane << 4)) ^ ((uint32_t)((wid & 7) << 4));

    for (int db = 0; db < 4; db++) {
        const int b0 = blockIdx.x * 8 + db * 2;
        const int nb = (db + 1) & 3;
        const int b0n = blockIdx.x * 8 + nb * 2;
        const float* psm = psmbuf + (db & 1) * 32;

        // ---- early gmem prefetches ----
        float4 pf[4];
        {
            const float* src = g_AB + (size_t)b0n * 4096;
#pragma unroll
            for (int q = 0; q < 4; q++) {
                int item = t2 + q*256;
                int row = item >> 6, f4 = (item & 63) + half*64;
                pf[q] = *(const float4*)(src + row*512 + f4*4);
            }
        }
        float psm_pf = 0.f;
        if (tid < 32)
            psm_pf = s[((size_t)(b0n + (tid>>4)) * 8 + ((tid>>1)&7)) * 64 + (tid & 1)];
        float gsd[8];
        if (half && t2 < 128) {
            int bb = t2 >> 6, c = t2 & 63;
#pragma unroll
            for (int i = 0; i < 8; i++)
                gsd[i] = g_SD[(size_t)((b0 + bb)*8 + i) * 64 + c];
        }

        // ---- X build: own half, 16 iters, row = it*8 + (wid&7) ----
#pragma unroll
        for (int it = 0; it < 16; it++) {
            const int p_s = it*8 + (wid & 7);
            const int bbi = p_s >> 6, p = p_s & 63, i = p >> 3, j = p & 7;
            const float dx = psm[bbi*16 + 2*i]     - psm[bbi*16 + 2*j];
            const float dy = psm[bbi*16 + 2*i + 1] - psm[bbi*16 + 2*j + 1];
            const float d = dx*dx + dy*dy;
            const float* base = ABsf + bbi*4096 + half*256;
            float4 A4 = *(const float4*)(base + i*512 + lane*4);
            float4 B4 = *(const float4*)(base + j*512 + 128 + lane*4);
            uint4 o;
            o.x = f2tf32(eluf(A4.x + B4.x + fmaf(d, wd4.x, bv4.x)));
            o.y = f2tf32(eluf(A4.y + B4.y + fmaf(d, wd4.y, bv4.y)));
            o.z = f2tf32(eluf(A4.z + B4.z + fmaf(d, wd4.z, bv4.z)));
            o.w = f2tf32(eluf(A4.w + B4.w + fmaf(d, wd4.w, bv4.w)));
            *(uint4*)(smc + xbo + (uint32_t)(p_s * 512) + xoff) = o;
        }
        if (!half) asm volatile("bar.sync 1, 256;" ::: "memory");
        else       asm volatile("bar.sync 2, 256;" ::: "memory");

        // ---- GEMM: tf32 single-pass, 16 k-steps (own half) ----
        float d[4][2][4];
#pragma unroll
        for (int mt = 0; mt < 4; mt++)
#pragma unroll
            for (int nt = 0; nt < 2; nt++)
#pragma unroll
                for (int q = 0; q < 4; q++) d[mt][nt][q] = 0.f;

#pragma unroll
        for (int ks = 0; ks < 16; ks++) {
            const uint32_t kb = (uint32_t)(ks * 32);
            uint32_t b00 = *(const uint32_t*)(smc + wboff + ((kb + bklo) ^ bnsw));
            uint32_t b01 = *(const uint32_t*)(smc + wboff + ((kb + bklo + 16) ^ bnsw));
            uint32_t b10 = *(const uint32_t*)(smc + wboff + 4096 + ((kb + bklo) ^ bnsw));
            uint32_t b11 = *(const uint32_t*)(smc + wboff + 4096 + ((kb + bklo + 16) ^ bnsw));
#pragma unroll
            for (int mt = 0; mt < 4; mt++) {
                uint32_t a[4];
                ldsm4(a, abase + (uint32_t)(mt * 8192) + ((kb + aklane) ^ arsw));
                mma_tf32(d[mt][0], a, b00, b01);
                mma_tf32(d[mt][1], a, b10, b11);
            }
        }

        if (!half) {
            // pf store (rel cols read only by rel X-build — done) + psm
#pragma unroll
            for (int q = 0; q < 4; q++) {
                int item = t2 + q*256;
                int row = item >> 6, f4 = item & 63;
                *(float4*)(ABsf + row*512 + f4*4) = pf[q];
            }
            if (tid < 32) psmbuf[((db+1)&1)*32 + tid] = psm_pf;

            // elu in regs
#pragma unroll
            for (int mt = 0; mt < 4; mt++)
#pragma unroll
                for (int nt = 0; nt < 2; nt++)
#pragma unroll
                    for (int q = 0; q < 4; q++)
                        d[mt][nt][q] = eluf(d[mt][nt][q] + b1c[nt*2 + (q & 1)]);

            asm volatile("bar.sync 4, 512;" ::: "memory");   // wait atp

            // E3: rel scale by att + column reduce -> zv
            float at[4][2];
#pragma unroll
            for (int mt = 0; mt < 4; mt++) {
                at[mt][0] = ABsf[1280 + wm*64 + mt*16 + (lane >> 2)];
                at[mt][1] = ABsf[1280 + wm*64 + mt*16 + 8 + (lane >> 2)];
            }
            float z0 = 0.f, z1 = 0.f, z2 = 0.f, z3 = 0.f;
#pragma unroll
            for (int mt = 0; mt < 4; mt++) {
                z0 += d[mt][0][0]*at[mt][0] + d[mt][0][2]*at[mt][1];
                z1 += d[mt][0][1]*at[mt][0] + d[mt][0][3]*at[mt][1];
                z2 += d[mt][1][0]*at[mt][0] + d[mt][1][2]*at[mt][1];
                z3 += d[mt][1][1]*at[mt][0] + d[mt][1][3]*at[mt][1];
            }
#pragma unroll
            for (int m = 4; m <= 16; m <<= 1) {
                z0 += __shfl_xor_sync(0xffffffffu, z0, m);
                z1 += __shfl_xor_sync(0xffffffffu, z1, m);
                z2 += __shfl_xor_sync(0xffffffffu, z2, m);
                z3 += __shfl_xor_sync(0xffffffffu, z3, m);
            }
            if (lane < 4) {
                zv[wm*64 + c0]     = z0;
                zv[wm*64 + c0 + 1] = z1;
                zv[wm*64 + c0 + 8] = z2;
                zv[wm*64 + c0 + 9] = z3;
            }
            asm volatile("bar.arrive 5, 512;" ::: "memory"); // zv ready
        } else {
            // E1: att partial dots -> attp (alias, att cols rows 0-1)
#pragma unroll
            for (int mt = 0; mt < 4; mt++) {
#pragma unroll
                for (int h = 0; h < 2; h++) {
                    float v0 = eluf(d[mt][0][h*2]     + b1c[0]);
                    float v1 = eluf(d[mt][0][h*2 + 1] + b1c[1]);
                    float v2 = eluf(d[mt][1][h*2]     + b1c[2]);
                    float v3 = eluf(d[mt][1][h*2 + 1] + b1c[3]);
                    float part = v0*w2c[0] + v1*w2c[1] + v2*w2c[2] + v3*w2c[3];
                    part += __shfl_xor_sync(0xffffffffu, part, 1);
                    part += __shfl_xor_sync(0xffffffffu, part, 2);
                    if ((lane & 3) == 0) {
                        int idx = wn*128 + wm*64 + mt*16 + h*8 + (lane >> 2);
                        ABsf[(idx >> 8)*512 + 256 + (idx & 255)] = part;
                    }
                }
            }
            asm volatile("bar.sync 3, 256;" ::: "memory");

            // E2: finalize att (sigmoid, diag mask) -> atp (alias, row 2 att cols)
            if (t2 < 128) {
                const int p = t2 & 63, i = p >> 3, j = p & 7;
                float a = ABsf[256 + t2]          // attp[t2]
                        + ABsf[384 + t2]          // attp[128 + t2]
                        + ABsf[768 + t2]          // attp[256 + t2]
                        + ABsf[896 + t2]          // attp[384 + t2]
                        + b2a;
                ABsf[1280 + t2] = (i == j) ? 0.f : 1.f / (1.f + __expf(-a));
            }
            asm volatile("bar.arrive 4, 512;" ::: "memory"); // atp ready
            asm volatile("bar.sync 5, 512;" ::: "memory");   // wait zv

            // E4: output
            if (t2 < 128) {
                const int bb = t2 >> 6, c = t2 & 63;
                float a0 = 0.f;
#pragma unroll
                for (int p = 0; p < 64; p++) a0 += ABsf[1280 + bb*64 + p];
                float sd = gsd[0] + gsd[1] + gsd[2] + gsd[3]
                         + gsd[4] + gsd[5] + gsd[6] + gsd[7];
                float o = zv[t2] + a0 * b2r_s[c] + sd;
#pragma unroll
                for (int k = 0; k < 64; k++)
                    o = fmaf(zv[bb*64 + k], W_rel2[k*64 + c], o);
                out[(size_t)(b0 + bb) * 64 + c] = o;
            }
            // FIX (R9 race): order E4's atp reads (warps 8-11) before the pf
            // store below, whose q=0, t2 in [128,192) items (warps 12-13)
            // overwrite row-2 att cols = the atp alias region.
            asm volatile("bar.sync 3, 256;" ::: "memory");

            // pf store (att cols; clobbers attp/atp — both dead now)
#pragma unroll
            for (int q = 0; q < 4; q++) {
                int item = t2 + q*256;
                int row = item >> 6, f4 = 64 + (item & 63);
                *(float4*)(ABsf + row*512 + f4*4) = pf[q];
            }
        }
        __syncthreads();
    }
}

// ---------------------------------------------------------------------------
extern "C" void kernel_launch(void* const* d_in, const int* in_sizes, int n_in,
                              void* d_out, int out_size)
{
    const float* s       = (const float*)d_in[0];
    const float* W_enc   = (const float*)d_in[1];
    const float* b_enc   = (const float*)d_in[2];
    const float* W_self0 = (const float*)d_in[3];
    const float* b_self0 = (const float*)d_in[4];
    const float* W_self1 = (const float*)d_in[5];
    const float* b_self1 = (const float*)d_in[6];
    const float* W_rel0  = (const float*)d_in[7];
    const float* b_rel0  = (const float*)d_in[8];
    const float* W_rel1  = (const float*)d_in[9];
    const float* b_rel1  = (const float*)d_in[10];
    const float* W_rel2  = (const float*)d_in[11];
    const float* b_rel2  = (const float*)d_in[12];
    const float* W_att0  = (const float*)d_in[13];
    const float* b_att0  = (const float*)d_in[14];
    const float* W_att1  = (const float*)d_in[15];
    const float* b_att1  = (const float*)d_in[16];
    const float* W_att2  = (const float*)d_in[17];
    const float* b_att2  = (const float*)d_in[18];
    float* out = (float*)d_out;

    cudaFuncSetAttribute(k1_kernel, cudaFuncAttributeMaxDynamicSharedMemorySize, SMEM1_BYTES);
    cudaFuncSetAttribute(k2_kernel, cudaFuncAttributeMaxDynamicSharedMemorySize, SMEM2_BYTES);

    k0_kernel<<<88, 256>>>(W_enc, W_self0, W_self1, W_rel0, W_att0);
    k1_kernel<<<ROWS/128, 512, SMEM1_BYTES>>>(s, b_enc, b_self0, b_self1);
    k2_kernel<<<BATCH/8, 512, SMEM2_BYTES>>>(s, W_rel0, b_rel0, W_rel1, b_rel1,
                                             W_rel2, b_rel2, W_att0, b_att0,
                                             W_att1, b_att1, W_att2, b_att2, out);
}